// round 1
// baseline (speedup 1.0000x reference)
#include <cuda_runtime.h>
#include <math.h>

#define BB   4
#define TT   2048
#define CC   1024
#define NH   16
#define NKV  4
#define HD   64
#define NTOK (BB*TT)
#define GATE_CH 12

// ---------------- scratch (static device allocations; no cudaMalloc) --------
__device__ float g_qraw[NTOK*CC];        // [n][H*D]  pre-rotary q
__device__ float g_kraw[NTOK*NKV*HD];    // [n][KV*D] pre-rotary k
__device__ float g_vraw[NTOK*NKV*HD];    // [n][KV*D] pre-gate v
__device__ float g_qn[NTOK*CC];          // [B,H,T,D]
__device__ float g_kn[NTOK*NKV*HD];      // [B,KV,T,D]
__device__ float g_vn[NTOK*NKV*HD];      // [B,KV,T,D]
__device__ float g_att[NTOK*CC];         // [B,T,H*D] attention output

// ---------------- fp32 NT GEMM: out[M,N] = A[M,K] * W[N,K]^T ----------------
// 64x64 tile, BK=16, 256 threads, 4x4 per thread.
__global__ __launch_bounds__(256) void gemm_nt(const float* __restrict__ A,
                                               const float* __restrict__ W,
                                               float* __restrict__ out,
                                               int M, int N, int K) {
    __shared__ float sA[16][68];   // [k][m]
    __shared__ float sB[16][68];   // [k][n]
    const int tid  = threadIdx.x;
    const int m0   = blockIdx.y * 64;
    const int n0   = blockIdx.x * 64;
    const int rg   = tid >> 4;     // 0..15 -> rows rg*4..+3
    const int cg   = tid & 15;     // 0..15 -> cols cg*4..+3
    const int lrow = tid >> 2;     // 0..63 load row
    const int lc4  = tid & 3;      // 0..3  load float4 within 16 k

    float acc[4][4];
#pragma unroll
    for (int i = 0; i < 4; i++)
#pragma unroll
        for (int j = 0; j < 4; j++) acc[i][j] = 0.f;

    for (int k0 = 0; k0 < K; k0 += 16) {
        float4 av = *(const float4*)(A + (size_t)(m0 + lrow) * K + k0 + lc4 * 4);
        float4 bv = *(const float4*)(W + (size_t)(n0 + lrow) * K + k0 + lc4 * 4);
        __syncthreads();   // previous tile's compute done before overwrite
        sA[lc4*4 + 0][lrow] = av.x;
        sA[lc4*4 + 1][lrow] = av.y;
        sA[lc4*4 + 2][lrow] = av.z;
        sA[lc4*4 + 3][lrow] = av.w;
        sB[lc4*4 + 0][lrow] = bv.x;
        sB[lc4*4 + 1][lrow] = bv.y;
        sB[lc4*4 + 2][lrow] = bv.z;
        sB[lc4*4 + 3][lrow] = bv.w;
        __syncthreads();
#pragma unroll
        for (int kk = 0; kk < 16; kk++) {
            float4 a4 = *(const float4*)&sA[kk][rg * 4];
            float4 b4 = *(const float4*)&sB[kk][cg * 4];
            float a[4] = {a4.x, a4.y, a4.z, a4.w};
            float b[4] = {b4.x, b4.y, b4.z, b4.w};
#pragma unroll
            for (int i = 0; i < 4; i++)
#pragma unroll
                for (int j = 0; j < 4; j++) acc[i][j] += a[i] * b[j];
        }
    }
#pragma unroll
    for (int i = 0; i < 4; i++) {
        float4 o = make_float4(acc[i][0], acc[i][1], acc[i][2], acc[i][3]);
        *(float4*)(out + (size_t)(m0 + rg * 4 + i) * N + n0 + cg * 4) = o;
    }
}

// ---------------- rotary + rmsnorm + gated ve add + layout change -----------
__device__ __forceinline__ void rope_norm(const float* __restrict__ in,
                                          float* __restrict__ outp,
                                          int t, int lane,
                                          const float* __restrict__ cosp,
                                          const float* __restrict__ sinp) {
    float x1 = in[lane];
    float x2 = in[32 + lane];
    float c  = cosp[t * 32 + lane];
    float s  = sinp[t * 32 + lane];
    float o1 =  x1 * c + x2 * s;
    float o2 = -x1 * s + x2 * c;
    float ss = o1 * o1 + o2 * o2;
#pragma unroll
    for (int off = 16; off; off >>= 1) ss += __shfl_xor_sync(0xffffffffu, ss, off);
    float r = rsqrtf(ss * (1.0f / HD) + 1e-6f) * 1.15f;
    outp[lane]      = o1 * r;
    outp[32 + lane] = o2 * r;
}

__global__ __launch_bounds__(256) void postproc(const float* __restrict__ x,
                                                const float* __restrict__ ve,
                                                const float* __restrict__ cosp,
                                                const float* __restrict__ sinp,
                                                const float* __restrict__ wgate) {
    const int n = blockIdx.x;            // token index
    const int b = n / TT;
    const int t = n % TT;
    const int w    = threadIdx.x >> 5;
    const int lane = threadIdx.x & 31;

    // 16 q heads across 8 warps (2 each)
#pragma unroll
    for (int h = w; h < NH; h += 8) {
        size_t obase = (((size_t)b * NH + h) * TT + t) * HD;
        rope_norm(g_qraw + (size_t)n * CC + h * HD, g_qn + obase, t, lane, cosp, sinp);
    }
    if (w < 4) {
        int h = w;  // kv head
        size_t obase = (((size_t)b * NKV + h) * TT + t) * HD;
        rope_norm(g_kraw + (size_t)n * NKV * HD + h * HD, g_kn + obase, t, lane, cosp, sinp);
    } else {
        int h = w - 4;  // kv head for v
        float g = (lane < GATE_CH)
                    ? x[(size_t)n * CC + lane] * wgate[h * GATE_CH + lane] : 0.f;
#pragma unroll
        for (int off = 16; off; off >>= 1) g += __shfl_xor_sync(0xffffffffu, g, off);
        g = 3.f / (1.f + __expf(-g));
        size_t ibase = (size_t)n * NKV * HD + h * HD;
        size_t obase = (((size_t)b * NKV + h) * TT + t) * HD;
        g_vn[obase + lane]      = g_vraw[ibase + lane]      + g * ve[ibase + lane];
        g_vn[obase + 32 + lane] = g_vraw[ibase + 32 + lane] + g * ve[ibase + 32 + lane];
    }
}

// ---------------- sliding-window flash attention (fp32) ---------------------
// grid: (T/64, B*H), 256 threads. Each thread: 4x4 S block + 4x4 O block.
#define STR 68
__global__ __launch_bounds__(256) void attn(const float* __restrict__ q,
                                            const float* __restrict__ k,
                                            const float* __restrict__ v,
                                            const int* __restrict__ winp,
                                            float* __restrict__ y) {
    extern __shared__ float sm[];
    float* sQ  = sm;                 // [r][d]   64x68
    float* sKt = sQ  + 64 * STR;     // [d][c]   (K transposed)
    float* sV  = sKt + 64 * STR;     // [c][d]
    float* sP  = sV  + 64 * STR;     // [r][c]

    const int tid = threadIdx.x;
    const int qt  = blockIdx.x;
    const int bh  = blockIdx.y;
    const int b   = bh / NH;
    const int h   = bh % NH;
    const int kvh = h >> 2;          // rep = H/KV = 4
    const int q0  = qt * 64;
    const int win = winp[0];
    const float scale = 0.125f;      // D^-0.5

    const int rg = tid >> 4;         // row group (4 rows)
    const int cg = tid & 15;         // col group (4 cols)

    // load Q tile
    {
        size_t qb = (((size_t)b * NH + h) * TT + q0) * HD;
#pragma unroll
        for (int l = 0; l < 4; l++) {
            int idx = tid + l * 256;
            int row = idx >> 4, c4 = idx & 15;
            float4 val = *(const float4*)(q + qb + (size_t)row * HD + c4 * 4);
            *(float4*)&sQ[row * STR + c4 * 4] = val;
        }
    }

    float m_i[4], l_i[4], acc[4][4];
#pragma unroll
    for (int i = 0; i < 4; i++) {
        m_i[i] = -1e30f; l_i[i] = 0.f;
#pragma unroll
        for (int j = 0; j < 4; j++) acc[i][j] = 0.f;
    }

    int kstart = q0 - win; if (kstart < 0) kstart = 0;
    const int kt0 = kstart >> 6;
    const int kt1 = q0 >> 6;

    for (int kt = kt0; kt <= kt1; kt++) {
        const int k0 = kt * 64;
        size_t kb = (((size_t)b * NKV + kvh) * TT + k0) * HD;
        __syncthreads();   // previous PV done (also covers first-iter Q visibility via next sync)
#pragma unroll
        for (int l = 0; l < 4; l++) {
            int idx = tid + l * 256;
            int row = idx >> 4, c4 = idx & 15;
            float4 kv4 = *(const float4*)(k + kb + (size_t)row * HD + c4 * 4);
            sKt[(c4 * 4 + 0) * STR + row] = kv4.x;
            sKt[(c4 * 4 + 1) * STR + row] = kv4.y;
            sKt[(c4 * 4 + 2) * STR + row] = kv4.z;
            sKt[(c4 * 4 + 3) * STR + row] = kv4.w;
            float4 vv = *(const float4*)(v + kb + (size_t)row * HD + c4 * 4);
            *(float4*)&sV[row * STR + c4 * 4] = vv;
        }
        __syncthreads();

        // S = Q K^T
        float s[4][4];
#pragma unroll
        for (int i = 0; i < 4; i++)
#pragma unroll
            for (int j = 0; j < 4; j++) s[i][j] = 0.f;
#pragma unroll 8
        for (int kk = 0; kk < 64; kk++) {
            float4 b4 = *(const float4*)&sKt[kk * STR + cg * 4];
#pragma unroll
            for (int i = 0; i < 4; i++) {
                float a = sQ[(rg * 4 + i) * STR + kk];
                s[i][0] += a * b4.x;
                s[i][1] += a * b4.y;
                s[i][2] += a * b4.z;
                s[i][3] += a * b4.w;
            }
        }

        // mask + scale
#pragma unroll
        for (int i = 0; i < 4; i++)
#pragma unroll
            for (int j = 0; j < 4; j++) {
                int diff = (q0 + rg * 4 + i) - (k0 + cg * 4 + j);
                bool valid = (diff >= 0) && (diff <= win);
                s[i][j] = valid ? s[i][j] * scale : -1e30f;
            }

        // row max across the 16 threads of this row group
        float mt[4];
#pragma unroll
        for (int i = 0; i < 4; i++) {
            float mm = s[i][0];
            mm = fmaxf(mm, s[i][1]); mm = fmaxf(mm, s[i][2]); mm = fmaxf(mm, s[i][3]);
            mt[i] = mm;
        }
#pragma unroll
        for (int off = 8; off; off >>= 1)
#pragma unroll
            for (int i = 0; i < 4; i++)
                mt[i] = fmaxf(mt[i], __shfl_xor_sync(0xffffffffu, mt[i], off));

        float mnew[4], alpha[4], rs[4];
#pragma unroll
        for (int i = 0; i < 4; i++) {
            mnew[i]  = fmaxf(m_i[i], mt[i]);
            alpha[i] = __expf(m_i[i] - mnew[i]);
            rs[i] = 0.f;
        }
        // p = exp(s - mnew)  (explicit 0 for masked to avoid -inf/-inf issues)
#pragma unroll
        for (int i = 0; i < 4; i++)
#pragma unroll
            for (int j = 0; j < 4; j++) {
                float p = (s[i][j] > -1e29f) ? __expf(s[i][j] - mnew[i]) : 0.f;
                s[i][j] = p;
                rs[i] += p;
            }
#pragma unroll
        for (int off = 8; off; off >>= 1)
#pragma unroll
            for (int i = 0; i < 4; i++)
                rs[i] += __shfl_xor_sync(0xffffffffu, rs[i], off);

#pragma unroll
        for (int i = 0; i < 4; i++) {
            l_i[i] = l_i[i] * alpha[i] + rs[i];
            m_i[i] = mnew[i];
#pragma unroll
            for (int j = 0; j < 4; j++) acc[i][j] *= alpha[i];
            *(float4*)&sP[(rg * 4 + i) * STR + cg * 4] =
                make_float4(s[i][0], s[i][1], s[i][2], s[i][3]);
        }
        __syncthreads();

        // O += P V
#pragma unroll 8
        for (int kk = 0; kk < 64; kk++) {
            float4 b4 = *(const float4*)&sV[kk * STR + cg * 4];
#pragma unroll
            for (int i = 0; i < 4; i++) {
                float a = sP[(rg * 4 + i) * STR + kk];
                acc[i][0] += a * b4.x;
                acc[i][1] += a * b4.y;
                acc[i][2] += a * b4.z;
                acc[i][3] += a * b4.w;
            }
        }
    }

    // epilogue: normalize and store to [B,T,H*D]
#pragma unroll
    for (int i = 0; i < 4; i++) {
        float inv = 1.0f / l_i[i];
        float4 o = make_float4(acc[i][0] * inv, acc[i][1] * inv,
                               acc[i][2] * inv, acc[i][3] * inv);
        *(float4*)(y + ((size_t)b * TT + q0 + rg * 4 + i) * CC + h * HD + cg * 4) = o;
    }
}

// ---------------- launcher ---------------------------------------------------
extern "C" void kernel_launch(void* const* d_in, const int* in_sizes, int n_in,
                              void* d_out, int out_size) {
    const float* x    = (const float*)d_in[0];
    const float* ve   = (const float*)d_in[1];
    const float* cosp = (const float*)d_in[2];
    const float* sinp = (const float*)d_in[3];
    const float* wq   = (const float*)d_in[4];
    const float* wk   = (const float*)d_in[5];
    const float* wv   = (const float*)d_in[6];
    const float* wo   = (const float*)d_in[7];
    const float* wg   = (const float*)d_in[8];
    const int*   win  = (const int*)d_in[9];
    float* out = (float*)d_out;

    float *qraw, *kraw, *vraw, *qn, *kn, *vn, *att;
    cudaGetSymbolAddress((void**)&qraw, g_qraw);
    cudaGetSymbolAddress((void**)&kraw, g_kraw);
    cudaGetSymbolAddress((void**)&vraw, g_vraw);
    cudaGetSymbolAddress((void**)&qn,   g_qn);
    cudaGetSymbolAddress((void**)&kn,   g_kn);
    cudaGetSymbolAddress((void**)&vn,   g_vn);
    cudaGetSymbolAddress((void**)&att,  g_att);

    // QKV projections
    gemm_nt<<<dim3(CC / 64, NTOK / 64), 256>>>(x, wq, qraw, NTOK, CC, CC);
    gemm_nt<<<dim3((NKV * HD) / 64, NTOK / 64), 256>>>(x, wk, kraw, NTOK, NKV * HD, CC);
    gemm_nt<<<dim3((NKV * HD) / 64, NTOK / 64), 256>>>(x, wv, vraw, NTOK, NKV * HD, CC);

    // rotary + rmsnorm + gated ve
    postproc<<<NTOK, 256>>>(x, ve, cosp, sinp, wg);

    // attention
    int smem = 4 * 64 * STR * (int)sizeof(float);  // 69632 B
    cudaFuncSetAttribute(attn, cudaFuncAttributeMaxDynamicSharedMemorySize, smem);
    attn<<<dim3(TT / 64, BB * NH), 256, smem>>>(qn, kn, vn, win, att);

    // output projection
    gemm_nt<<<dim3(CC / 64, NTOK / 64), 256>>>(att, wo, out, NTOK, CC, CC);
}

// round 2
// speedup vs baseline: 2.9631x; 2.9631x over previous
#include <cuda_runtime.h>
#include <math.h>

#define BB   4
#define TT   2048
#define CC   1024
#define NH   16
#define NKV  4
#define HD   64
#define NTOK (BB*TT)
#define GATE_CH 12

// ---------------- scratch ----------------------------------------------------
__device__ float g_qraw[NTOK*CC];
__device__ float g_kraw[NTOK*NKV*HD];
__device__ float g_vraw[NTOK*NKV*HD];
__device__ float g_qn[NTOK*CC];          // [B,H,T,D]
__device__ float g_kn[NTOK*NKV*HD];      // [B,KV,T,D]
__device__ float g_vn[NTOK*NKV*HD];      // [B,KV,T,D]
__device__ float g_att[NTOK*CC];         // [B,T,H*D]

// ---------------- tf32 helpers ----------------------------------------------
__device__ __forceinline__ unsigned f2tf(float f) {
    unsigned u;
    asm("cvt.rna.tf32.f32 %0, %1;" : "=r"(u) : "f"(f));
    return u;
}
__device__ __forceinline__ void mma_tf32(float& d0, float& d1, float& d2, float& d3,
                                         unsigned a0, unsigned a1, unsigned a2, unsigned a3,
                                         unsigned b0, unsigned b1) {
    asm volatile(
        "mma.sync.aligned.m16n8k8.row.col.f32.tf32.tf32.f32 "
        "{%0,%1,%2,%3}, {%4,%5,%6,%7}, {%8,%9}, {%0,%1,%2,%3};"
        : "+f"(d0), "+f"(d1), "+f"(d2), "+f"(d3)
        : "r"(a0), "r"(a1), "r"(a2), "r"(a3), "r"(b0), "r"(b1));
}
__device__ __forceinline__ unsigned fu(float f) { return __float_as_uint(f); }

// ---------------- tf32 NT GEMM: out[M,N] = A[M,K] * W[N,K]^T -----------------
// block 128x128, BK=32, 256 threads = 8 warps (4m x 2n), warp tile 32x64.
#define GS 36
__global__ __launch_bounds__(256) void gemm_tf32(const float* __restrict__ A,
                                                 const float* __restrict__ W,
                                                 float* __restrict__ out,
                                                 int M, int N, int K) {
    __shared__ float sA[128 * GS];
    __shared__ float sB[128 * GS];
    const int tid  = threadIdx.x;
    const int lane = tid & 31;
    const int wid  = tid >> 5;
    const int m0 = blockIdx.y * 128, n0 = blockIdx.x * 128;
    const int wm = (wid >> 1) * 32, wn = (wid & 1) * 64;
    const int g = lane >> 2, t = lane & 3;
    const int lrow = tid >> 3, lc4 = tid & 7;

    float acc[2][8][4];
#pragma unroll
    for (int i = 0; i < 2; i++)
#pragma unroll
        for (int j = 0; j < 8; j++)
#pragma unroll
            for (int e = 0; e < 4; e++) acc[i][j][e] = 0.f;

    for (int k0 = 0; k0 < K; k0 += 32) {
        float4 av[4], bv[4];
#pragma unroll
        for (int l = 0; l < 4; l++) {
            int row = lrow + 32 * l;
            av[l] = *(const float4*)(A + (size_t)(m0 + row) * K + k0 + lc4 * 4);
            bv[l] = *(const float4*)(W + (size_t)(n0 + row) * K + k0 + lc4 * 4);
        }
        __syncthreads();
#pragma unroll
        for (int l = 0; l < 4; l++) {
            int base = (lrow + 32 * l) * GS + lc4 * 4;
            sA[base + 0] = __uint_as_float(f2tf(av[l].x));
            sA[base + 1] = __uint_as_float(f2tf(av[l].y));
            sA[base + 2] = __uint_as_float(f2tf(av[l].z));
            sA[base + 3] = __uint_as_float(f2tf(av[l].w));
            sB[base + 0] = __uint_as_float(f2tf(bv[l].x));
            sB[base + 1] = __uint_as_float(f2tf(bv[l].y));
            sB[base + 2] = __uint_as_float(f2tf(bv[l].z));
            sB[base + 3] = __uint_as_float(f2tf(bv[l].w));
        }
        __syncthreads();
#pragma unroll
        for (int ks = 0; ks < 4; ks++) {
            const int kk = ks * 8;
            unsigned a[2][4];
#pragma unroll
            for (int i = 0; i < 2; i++) {
                int r = wm + i * 16 + g;
                a[i][0] = fu(sA[r * GS + kk + t]);
                a[i][1] = fu(sA[(r + 8) * GS + kk + t]);
                a[i][2] = fu(sA[r * GS + kk + t + 4]);
                a[i][3] = fu(sA[(r + 8) * GS + kk + t + 4]);
            }
            unsigned b[8][2];
#pragma unroll
            for (int j = 0; j < 8; j++) {
                int c = wn + j * 8 + g;
                b[j][0] = fu(sB[c * GS + kk + t]);
                b[j][1] = fu(sB[c * GS + kk + t + 4]);
            }
#pragma unroll
            for (int i = 0; i < 2; i++)
#pragma unroll
                for (int j = 0; j < 8; j++)
                    mma_tf32(acc[i][j][0], acc[i][j][1], acc[i][j][2], acc[i][j][3],
                             a[i][0], a[i][1], a[i][2], a[i][3], b[j][0], b[j][1]);
        }
    }
#pragma unroll
    for (int i = 0; i < 2; i++) {
        int r = m0 + wm + i * 16 + g;
#pragma unroll
        for (int j = 0; j < 8; j++) {
            int c = n0 + wn + j * 8 + 2 * t;
            *(float2*)(out + (size_t)r * N + c) = make_float2(acc[i][j][0], acc[i][j][1]);
            *(float2*)(out + (size_t)(r + 8) * N + c) = make_float2(acc[i][j][2], acc[i][j][3]);
        }
    }
}

// ---------------- rotary + rmsnorm + gated ve add + layout change ------------
__device__ __forceinline__ void rope_norm(const float* __restrict__ in,
                                          float* __restrict__ outp,
                                          int t, int lane,
                                          const float* __restrict__ cosp,
                                          const float* __restrict__ sinp) {
    float x1 = in[lane];
    float x2 = in[32 + lane];
    float c  = cosp[t * 32 + lane];
    float s  = sinp[t * 32 + lane];
    float o1 =  x1 * c + x2 * s;
    float o2 = -x1 * s + x2 * c;
    float ss = o1 * o1 + o2 * o2;
#pragma unroll
    for (int off = 16; off; off >>= 1) ss += __shfl_xor_sync(0xffffffffu, ss, off);
    float r = rsqrtf(ss * (1.0f / HD) + 1e-6f) * 1.15f;
    outp[lane]      = o1 * r;
    outp[32 + lane] = o2 * r;
}

__global__ __launch_bounds__(256) void postproc(const float* __restrict__ x,
                                                const float* __restrict__ ve,
                                                const float* __restrict__ cosp,
                                                const float* __restrict__ sinp,
                                                const float* __restrict__ wgate) {
    const int n = blockIdx.x;
    const int b = n / TT;
    const int t = n % TT;
    const int w    = threadIdx.x >> 5;
    const int lane = threadIdx.x & 31;

#pragma unroll
    for (int h = w; h < NH; h += 8) {
        size_t obase = (((size_t)b * NH + h) * TT + t) * HD;
        rope_norm(g_qraw + (size_t)n * CC + h * HD, g_qn + obase, t, lane, cosp, sinp);
    }
    if (w < 4) {
        int h = w;
        size_t obase = (((size_t)b * NKV + h) * TT + t) * HD;
        rope_norm(g_kraw + (size_t)n * NKV * HD + h * HD, g_kn + obase, t, lane, cosp, sinp);
    } else {
        int h = w - 4;
        float g = (lane < GATE_CH)
                    ? x[(size_t)n * CC + lane] * wgate[h * GATE_CH + lane] : 0.f;
#pragma unroll
        for (int off = 16; off; off >>= 1) g += __shfl_xor_sync(0xffffffffu, g, off);
        g = 3.f / (1.f + __expf(-g));
        size_t ibase = (size_t)n * NKV * HD + h * HD;
        size_t obase = (((size_t)b * NKV + h) * TT + t) * HD;
        g_vn[obase + lane]      = g_vraw[ibase + lane]      + g * ve[ibase + lane];
        g_vn[obase + 32 + lane] = g_vraw[ibase + 32 + lane] + g * ve[ibase + 32 + lane];
    }
}

// ---------------- tensor-core sliding-window flash attention -----------------
// grid (T/64, B*H), 128 threads = 4 warps; warp w owns rows w*16..w*16+15.
#define AS 72
__global__ __launch_bounds__(128) void attn_tc(const float* __restrict__ q,
                                               const float* __restrict__ k,
                                               const float* __restrict__ v,
                                               const int* __restrict__ winp,
                                               float* __restrict__ y) {
    extern __shared__ float sm[];
    float* sQ = sm;                // [r][d] 64x72 (tf32 bits)
    float* sK = sQ + 64 * AS;      // [c][d]
    float* sV = sK + 64 * AS;      // [c][d]
    float* sP = sV + 64 * AS;      // [r][c] (tf32 bits)

    const int tid  = threadIdx.x;
    const int lane = tid & 31;
    const int wid  = tid >> 5;
    const int g = lane >> 2, t = lane & 3;

    const int qt = blockIdx.x;
    const int bh = blockIdx.y;
    const int b  = bh >> 4;
    const int h  = bh & 15;
    const int kvh = h >> 2;
    const int q0  = qt * 64;
    const int win = winp[0];
    const float scale = 0.125f;

    // load + convert Q tile
    {
        size_t qb = (((size_t)b * NH + h) * TT + q0) * HD;
#pragma unroll
        for (int l = 0; l < 8; l++) {
            int idx = tid + l * 128;
            int row = idx >> 4, c4 = idx & 15;
            float4 v4 = *(const float4*)(q + qb + (size_t)row * HD + c4 * 4);
            int base = row * AS + c4 * 4;
            sQ[base + 0] = __uint_as_float(f2tf(v4.x));
            sQ[base + 1] = __uint_as_float(f2tf(v4.y));
            sQ[base + 2] = __uint_as_float(f2tf(v4.z));
            sQ[base + 3] = __uint_as_float(f2tf(v4.w));
        }
    }
    __syncthreads();

    // preload Q fragments (row block = wid*16)
    const int rw = wid * 16 + g;
    unsigned qa[8][4];
#pragma unroll
    for (int ks = 0; ks < 8; ks++) {
        int kk = ks * 8;
        qa[ks][0] = fu(sQ[rw * AS + kk + t]);
        qa[ks][1] = fu(sQ[(rw + 8) * AS + kk + t]);
        qa[ks][2] = fu(sQ[rw * AS + kk + t + 4]);
        qa[ks][3] = fu(sQ[(rw + 8) * AS + kk + t + 4]);
    }

    float accO[8][4];
#pragma unroll
    for (int j = 0; j < 8; j++)
#pragma unroll
        for (int e = 0; e < 4; e++) accO[j][e] = 0.f;
    float m1 = -1e30f, m2 = -1e30f, l1 = 0.f, l2 = 0.f;

    const int r1 = q0 + rw;        // global q row of c0/c1
    const int r2 = r1 + 8;         // global q row of c2/c3

    int kstart = q0 - win; if (kstart < 0) kstart = 0;
    const int kt0 = kstart >> 6;
    const int kt1 = q0 >> 6;

    for (int kt = kt0; kt <= kt1; kt++) {
        const int k0 = kt * 64;
        size_t kb = (((size_t)b * NKV + kvh) * TT + k0) * HD;
        __syncthreads();
#pragma unroll
        for (int l = 0; l < 8; l++) {
            int idx = tid + l * 128;
            int row = idx >> 4, c4 = idx & 15;
            float4 kv = *(const float4*)(k + kb + (size_t)row * HD + c4 * 4);
            float4 vv = *(const float4*)(v + kb + (size_t)row * HD + c4 * 4);
            int base = row * AS + c4 * 4;
            sK[base + 0] = __uint_as_float(f2tf(kv.x));
            sK[base + 1] = __uint_as_float(f2tf(kv.y));
            sK[base + 2] = __uint_as_float(f2tf(kv.z));
            sK[base + 3] = __uint_as_float(f2tf(kv.w));
            sV[base + 0] = __uint_as_float(f2tf(vv.x));
            sV[base + 1] = __uint_as_float(f2tf(vv.y));
            sV[base + 2] = __uint_as_float(f2tf(vv.z));
            sV[base + 3] = __uint_as_float(f2tf(vv.w));
        }
        __syncthreads();

        // S = Q K^T  (warp rows rw..rw+15, full 64 cols)
        float s[8][4];
#pragma unroll
        for (int j = 0; j < 8; j++)
#pragma unroll
            for (int e = 0; e < 4; e++) s[j][e] = 0.f;
#pragma unroll
        for (int ks = 0; ks < 8; ks++) {
            int kk = ks * 8;
            unsigned bb[8][2];
#pragma unroll
            for (int j = 0; j < 8; j++) {
                int c = j * 8 + g;
                bb[j][0] = fu(sK[c * AS + kk + t]);
                bb[j][1] = fu(sK[c * AS + kk + t + 4]);
            }
#pragma unroll
            for (int j = 0; j < 8; j++)
                mma_tf32(s[j][0], s[j][1], s[j][2], s[j][3],
                         qa[ks][0], qa[ks][1], qa[ks][2], qa[ks][3],
                         bb[j][0], bb[j][1]);
        }

        // scale + mask
#pragma unroll
        for (int j = 0; j < 8; j++)
#pragma unroll
            for (int e = 0; e < 4; e++) s[j][e] *= scale;
        bool edge = (kt == kt1) || (q0 + 63 - k0 > win);
        if (edge) {
#pragma unroll
            for (int j = 0; j < 8; j++) {
                int c0 = k0 + j * 8 + 2 * t;
                int d00 = r1 - c0, d01 = d00 - 1;
                int d10 = r2 - c0, d11 = d10 - 1;
                if (!(d00 >= 0 && d00 <= win)) s[j][0] = -1e30f;
                if (!(d01 >= 0 && d01 <= win)) s[j][1] = -1e30f;
                if (!(d10 >= 0 && d10 <= win)) s[j][2] = -1e30f;
                if (!(d11 >= 0 && d11 <= win)) s[j][3] = -1e30f;
            }
        }

        // row max over this tile
        float mt1 = -1e30f, mt2 = -1e30f;
#pragma unroll
        for (int j = 0; j < 8; j++) {
            mt1 = fmaxf(mt1, fmaxf(s[j][0], s[j][1]));
            mt2 = fmaxf(mt2, fmaxf(s[j][2], s[j][3]));
        }
        mt1 = fmaxf(mt1, __shfl_xor_sync(0xffffffffu, mt1, 1));
        mt1 = fmaxf(mt1, __shfl_xor_sync(0xffffffffu, mt1, 2));
        mt2 = fmaxf(mt2, __shfl_xor_sync(0xffffffffu, mt2, 1));
        mt2 = fmaxf(mt2, __shfl_xor_sync(0xffffffffu, mt2, 2));

        float mn1 = fmaxf(m1, mt1), mn2 = fmaxf(m2, mt2);
        float al1 = __expf(m1 - mn1), al2 = __expf(m2 - mn2);

        float rs1 = 0.f, rs2 = 0.f;
#pragma unroll
        for (int j = 0; j < 8; j++) {
            float p0 = (s[j][0] > -1e29f) ? __expf(s[j][0] - mn1) : 0.f;
            float p1 = (s[j][1] > -1e29f) ? __expf(s[j][1] - mn1) : 0.f;
            float p2 = (s[j][2] > -1e29f) ? __expf(s[j][2] - mn2) : 0.f;
            float p3 = (s[j][3] > -1e29f) ? __expf(s[j][3] - mn2) : 0.f;
            rs1 += p0 + p1; rs2 += p2 + p3;
            int cb = j * 8 + 2 * t;
            *(float2*)&sP[rw * AS + cb] =
                make_float2(__uint_as_float(f2tf(p0)), __uint_as_float(f2tf(p1)));
            *(float2*)&sP[(rw + 8) * AS + cb] =
                make_float2(__uint_as_float(f2tf(p2)), __uint_as_float(f2tf(p3)));
        }
        rs1 += __shfl_xor_sync(0xffffffffu, rs1, 1);
        rs1 += __shfl_xor_sync(0xffffffffu, rs1, 2);
        rs2 += __shfl_xor_sync(0xffffffffu, rs2, 1);
        rs2 += __shfl_xor_sync(0xffffffffu, rs2, 2);

        l1 = l1 * al1 + rs1; m1 = mn1;
        l2 = l2 * al2 + rs2; m2 = mn2;
#pragma unroll
        for (int j = 0; j < 8; j++) {
            accO[j][0] *= al1; accO[j][1] *= al1;
            accO[j][2] *= al2; accO[j][3] *= al2;
        }
        __syncwarp();

        // O += P V
#pragma unroll
        for (int ks = 0; ks < 8; ks++) {
            int kk = ks * 8;
            unsigned pa[4];
            pa[0] = fu(sP[rw * AS + kk + t]);
            pa[1] = fu(sP[(rw + 8) * AS + kk + t]);
            pa[2] = fu(sP[rw * AS + kk + t + 4]);
            pa[3] = fu(sP[(rw + 8) * AS + kk + t + 4]);
            unsigned bb[8][2];
#pragma unroll
            for (int j = 0; j < 8; j++) {
                int d = j * 8 + g;
                bb[j][0] = fu(sV[(kk + t) * AS + d]);
                bb[j][1] = fu(sV[(kk + t + 4) * AS + d]);
            }
#pragma unroll
            for (int j = 0; j < 8; j++)
                mma_tf32(accO[j][0], accO[j][1], accO[j][2], accO[j][3],
                         pa[0], pa[1], pa[2], pa[3], bb[j][0], bb[j][1]);
        }
    }

    // epilogue
    float il1 = 1.0f / l1, il2 = 1.0f / l2;
#pragma unroll
    for (int j = 0; j < 8; j++) {
        int d = h * HD + j * 8 + 2 * t;
        *(float2*)(y + ((size_t)b * TT + r1) * CC + d) =
            make_float2(accO[j][0] * il1, accO[j][1] * il1);
        *(float2*)(y + ((size_t)b * TT + r2) * CC + d) =
            make_float2(accO[j][2] * il2, accO[j][3] * il2);
    }
}

// ---------------- launcher ---------------------------------------------------
extern "C" void kernel_launch(void* const* d_in, const int* in_sizes, int n_in,
                              void* d_out, int out_size) {
    const float* x    = (const float*)d_in[0];
    const float* ve   = (const float*)d_in[1];
    const float* cosp = (const float*)d_in[2];
    const float* sinp = (const float*)d_in[3];
    const float* wq   = (const float*)d_in[4];
    const float* wk   = (const float*)d_in[5];
    const float* wv   = (const float*)d_in[6];
    const float* wo   = (const float*)d_in[7];
    const float* wg   = (const float*)d_in[8];
    const int*   win  = (const int*)d_in[9];
    float* out = (float*)d_out;

    float *qraw, *kraw, *vraw, *qn, *kn, *vn, *att;
    cudaGetSymbolAddress((void**)&qraw, g_qraw);
    cudaGetSymbolAddress((void**)&kraw, g_kraw);
    cudaGetSymbolAddress((void**)&vraw, g_vraw);
    cudaGetSymbolAddress((void**)&qn,   g_qn);
    cudaGetSymbolAddress((void**)&kn,   g_kn);
    cudaGetSymbolAddress((void**)&vn,   g_vn);
    cudaGetSymbolAddress((void**)&att,  g_att);

    // QKV projections (tensor cores, tf32)
    gemm_tf32<<<dim3(CC / 128, NTOK / 128), 256>>>(x, wq, qraw, NTOK, CC, CC);
    gemm_tf32<<<dim3((NKV * HD) / 128, NTOK / 128), 256>>>(x, wk, kraw, NTOK, NKV * HD, CC);
    gemm_tf32<<<dim3((NKV * HD) / 128, NTOK / 128), 256>>>(x, wv, vraw, NTOK, NKV * HD, CC);

    // rotary + rmsnorm + gated ve
    postproc<<<NTOK, 256>>>(x, ve, cosp, sinp, wg);

    // attention (tensor cores)
    int smem = 4 * 64 * AS * (int)sizeof(float);  // 73728 B
    cudaFuncSetAttribute(attn_tc, cudaFuncAttributeMaxDynamicSharedMemorySize, smem);
    attn_tc<<<dim3(TT / 64, BB * NH), 128, smem>>>(qn, kn, vn, win, att);

    // output projection
    gemm_tf32<<<dim3(CC / 128, NTOK / 128), 256>>>(att, wo, out, NTOK, CC, CC);
}

// round 3
// speedup vs baseline: 3.0704x; 1.0362x over previous
#include <cuda_runtime.h>
#include <math.h>

#define BB   4
#define TT   2048
#define CC   1024
#define NH   16
#define NKV  4
#define HD   64
#define NTOK (BB*TT)
#define GATE_CH 12

// ---------------- scratch ----------------------------------------------------
__device__ float g_qraw[NTOK*CC];
__device__ float g_kraw[NTOK*NKV*HD];
__device__ float g_vraw[NTOK*NKV*HD];
__device__ float g_qn[NTOK*CC];          // [B,H,T,D]  (scale folded in)
__device__ float g_kn[NTOK*NKV*HD];      // [B,KV,T,D]
__device__ float g_vn[NTOK*NKV*HD];      // [B,KV,T,D]
__device__ float g_att[NTOK*CC];         // [B,T,H*D]

// ---------------- helpers ----------------------------------------------------
__device__ __forceinline__ unsigned f2tf(float f) {
    unsigned u;
    asm("cvt.rna.tf32.f32 %0, %1;" : "=r"(u) : "f"(f));
    return u;
}
__device__ __forceinline__ float f2tff(float f) { return __uint_as_float(f2tf(f)); }
__device__ __forceinline__ unsigned fu(float f) { return __float_as_uint(f); }
__device__ __forceinline__ void mma_tf32(float& d0, float& d1, float& d2, float& d3,
                                         unsigned a0, unsigned a1, unsigned a2, unsigned a3,
                                         unsigned b0, unsigned b1) {
    asm volatile(
        "mma.sync.aligned.m16n8k8.row.col.f32.tf32.tf32.f32 "
        "{%0,%1,%2,%3}, {%4,%5,%6,%7}, {%8,%9}, {%0,%1,%2,%3};"
        : "+f"(d0), "+f"(d1), "+f"(d2), "+f"(d3)
        : "r"(a0), "r"(a1), "r"(a2), "r"(a3), "r"(b0), "r"(b1));
}
__device__ __forceinline__ void cpa16(float* s, const float* g) {
    unsigned sa = (unsigned)__cvta_generic_to_shared(s);
    asm volatile("cp.async.cg.shared.global [%0], [%1], 16;" :: "r"(sa), "l"(g));
}
__device__ __forceinline__ void cp_commit() { asm volatile("cp.async.commit_group;"); }
__device__ __forceinline__ void cp_wait0()  { asm volatile("cp.async.wait_group 0;"); }

// ---------------- tf32 NT GEMM body: out[M,N] = A[M,K] * W[N,K]^T ------------
// block tile 128x128, BK=32, 256 threads = 8 warps (4m x 2n), warp tile 32x64.
// Register-prefetch pipeline: STS(i) -> LDG(i+1) -> compute(i).
#define GS 36
__device__ __forceinline__ void gemm_body(const float* __restrict__ A,
                                          const float* __restrict__ W,
                                          float* __restrict__ out,
                                          int N, int K, int m0, int n0) {
    __shared__ float sA[128 * GS];
    __shared__ float sB[128 * GS];
    const int tid  = threadIdx.x;
    const int lane = tid & 31;
    const int wid  = tid >> 5;
    const int wm = (wid >> 1) * 32, wn = (wid & 1) * 64;
    const int g = lane >> 2, t = lane & 3;
    const int lrow = tid >> 3, lc4 = tid & 7;

    float acc[2][8][4];
#pragma unroll
    for (int i = 0; i < 2; i++)
#pragma unroll
        for (int j = 0; j < 8; j++)
#pragma unroll
            for (int e = 0; e < 4; e++) acc[i][j][e] = 0.f;

    float4 av[4], bv[4];
#pragma unroll
    for (int l = 0; l < 4; l++) {
        int row = lrow + 32 * l;
        av[l] = *(const float4*)(A + (size_t)(m0 + row) * K + lc4 * 4);
        bv[l] = *(const float4*)(W + (size_t)(n0 + row) * K + lc4 * 4);
    }

    for (int k0 = 0; k0 < K; k0 += 32) {
        __syncthreads();
#pragma unroll
        for (int l = 0; l < 4; l++) {
            int base = (lrow + 32 * l) * GS + lc4 * 4;
            sA[base + 0] = f2tff(av[l].x);
            sA[base + 1] = f2tff(av[l].y);
            sA[base + 2] = f2tff(av[l].z);
            sA[base + 3] = f2tff(av[l].w);
            sB[base + 0] = f2tff(bv[l].x);
            sB[base + 1] = f2tff(bv[l].y);
            sB[base + 2] = f2tff(bv[l].z);
            sB[base + 3] = f2tff(bv[l].w);
        }
        __syncthreads();
        if (k0 + 32 < K) {
#pragma unroll
            for (int l = 0; l < 4; l++) {
                int row = lrow + 32 * l;
                av[l] = *(const float4*)(A + (size_t)(m0 + row) * K + k0 + 32 + lc4 * 4);
                bv[l] = *(const float4*)(W + (size_t)(n0 + row) * K + k0 + 32 + lc4 * 4);
            }
        }
#pragma unroll
        for (int ks = 0; ks < 4; ks++) {
            const int kk = ks * 8;
            unsigned a[2][4];
#pragma unroll
            for (int i = 0; i < 2; i++) {
                int r = wm + i * 16 + g;
                a[i][0] = fu(sA[r * GS + kk + t]);
                a[i][1] = fu(sA[(r + 8) * GS + kk + t]);
                a[i][2] = fu(sA[r * GS + kk + t + 4]);
                a[i][3] = fu(sA[(r + 8) * GS + kk + t + 4]);
            }
            unsigned b[8][2];
#pragma unroll
            for (int j = 0; j < 8; j++) {
                int c = wn + j * 8 + g;
                b[j][0] = fu(sB[c * GS + kk + t]);
                b[j][1] = fu(sB[c * GS + kk + t + 4]);
            }
#pragma unroll
            for (int i = 0; i < 2; i++)
#pragma unroll
                for (int j = 0; j < 8; j++)
                    mma_tf32(acc[i][j][0], acc[i][j][1], acc[i][j][2], acc[i][j][3],
                             a[i][0], a[i][1], a[i][2], a[i][3], b[j][0], b[j][1]);
        }
    }
#pragma unroll
    for (int i = 0; i < 2; i++) {
        int r = m0 + wm + i * 16 + g;
#pragma unroll
        for (int j = 0; j < 8; j++) {
            int c = n0 + wn + j * 8 + 2 * t;
            *(float2*)(out + (size_t)r * N + c) = make_float2(acc[i][j][0], acc[i][j][1]);
            *(float2*)(out + (size_t)(r + 8) * N + c) = make_float2(acc[i][j][2], acc[i][j][3]);
        }
    }
}

__global__ __launch_bounds__(256) void gemm_tf32(const float* __restrict__ A,
                                                 const float* __restrict__ W,
                                                 float* __restrict__ out,
                                                 int N, int K) {
    gemm_body(A, W, out, N, K, blockIdx.y * 128, blockIdx.x * 128);
}

// fused K+V projection: blockIdx.x 0..3 -> (wk n0=0), (wk n0=128), (wv 0), (wv 128)
__global__ __launch_bounds__(256) void gemm_kv(const float* __restrict__ A,
                                               const float* __restrict__ wk,
                                               const float* __restrict__ wv,
                                               float* __restrict__ kout,
                                               float* __restrict__ vout) {
    const bool isv = blockIdx.x >= 2;
    gemm_body(A, isv ? wv : wk, isv ? vout : kout,
              NKV * HD, CC, blockIdx.y * 128, (blockIdx.x & 1) * 128);
}

// ---------------- rotary + rmsnorm + gated ve add + layout change ------------
__device__ __forceinline__ void rope_norm(const float* __restrict__ in,
                                          float* __restrict__ outp,
                                          int t, int lane, float mult,
                                          const float* __restrict__ cosp,
                                          const float* __restrict__ sinp) {
    float x1 = in[lane];
    float x2 = in[32 + lane];
    float c  = cosp[t * 32 + lane];
    float s  = sinp[t * 32 + lane];
    float o1 =  x1 * c + x2 * s;
    float o2 = -x1 * s + x2 * c;
    float ss = o1 * o1 + o2 * o2;
#pragma unroll
    for (int off = 16; off; off >>= 1) ss += __shfl_xor_sync(0xffffffffu, ss, off);
    float r = rsqrtf(ss * (1.0f / HD) + 1e-6f) * mult;
    outp[lane]      = o1 * r;
    outp[32 + lane] = o2 * r;
}

__global__ __launch_bounds__(256) void postproc(const float* __restrict__ x,
                                                const float* __restrict__ ve,
                                                const float* __restrict__ cosp,
                                                const float* __restrict__ sinp,
                                                const float* __restrict__ wgate) {
    const int n = blockIdx.x;
    const int b = n / TT;
    const int t = n % TT;
    const int w    = threadIdx.x >> 5;
    const int lane = threadIdx.x & 31;

    // q: fold softmax scale 0.125 into the 1.15 rms multiplier
#pragma unroll
    for (int h = w; h < NH; h += 8) {
        size_t obase = (((size_t)b * NH + h) * TT + t) * HD;
        rope_norm(g_qraw + (size_t)n * CC + h * HD, g_qn + obase, t, lane,
                  1.15f * 0.125f, cosp, sinp);
    }
    if (w < 4) {
        int h = w;
        size_t obase = (((size_t)b * NKV + h) * TT + t) * HD;
        rope_norm(g_kraw + (size_t)n * NKV * HD + h * HD, g_kn + obase, t, lane,
                  1.15f, cosp, sinp);
    } else {
        int h = w - 4;
        float g = (lane < GATE_CH)
                    ? x[(size_t)n * CC + lane] * wgate[h * GATE_CH + lane] : 0.f;
#pragma unroll
        for (int off = 16; off; off >>= 1) g += __shfl_xor_sync(0xffffffffu, g, off);
        g = 3.f / (1.f + __expf(-g));
        size_t ibase = (size_t)n * NKV * HD + h * HD;
        size_t obase = (((size_t)b * NKV + h) * TT + t) * HD;
        g_vn[obase + lane]      = g_vraw[ibase + lane]      + g * ve[ibase + lane];
        g_vn[obase + 32 + lane] = g_vraw[ibase + 32 + lane] + g * ve[ibase + 32 + lane];
    }
}

// ---------------- tensor-core sliding-window flash attention -----------------
// grid (T/128, B*H), 256 threads = 8 warps; warp w owns q rows w*16..w*16+15.
// K/V double-buffered via cp.async; sP aliases sQ.
#define AS 72
#define QT 128
#define KVSTG (64 * AS)
__global__ __launch_bounds__(256) void attn_tc(const float* __restrict__ q,
                                               const float* __restrict__ k,
                                               const float* __restrict__ v,
                                               const int* __restrict__ winp,
                                               float* __restrict__ y) {
    extern __shared__ float sm[];
    float* sQ = sm;                    // [r][d] 128x72 (tf32)  — dead after frag load
    float* sP = sm;                    // [r][c] 128x72 (tf32)  — aliases sQ
    float* sK = sm + QT * AS;          // 2 stages of [c][d] 64x72
    float* sV = sK + 2 * KVSTG;        // 2 stages of [c][d] 64x72

    const int tid  = threadIdx.x;
    const int lane = tid & 31;
    const int wid  = tid >> 5;
    const int g = lane >> 2, t = lane & 3;

    const int qt = blockIdx.x;
    const int bh = blockIdx.y;
    const int b  = bh >> 4;
    const int h  = bh & 15;
    const int kvh = h >> 2;
    const int q0  = qt * QT;
    const int win = winp[0];

    int kstart = q0 - win; if (kstart < 0) kstart = 0;
    const int kt0 = kstart >> 6;
    const int kt1 = (q0 + QT - 1) >> 6;

    const size_t kvbase = ((size_t)b * NKV + kvh) * TT;

    // prologue: start first K/V tile load immediately
    {
        const int k0 = kt0 * 64;
        size_t kb = (kvbase + k0) * HD;
#pragma unroll
        for (int l = 0; l < 4; l++) {
            int idx = tid + l * 256;
            int row = idx >> 4, c4 = idx & 15;
            cpa16(&sK[row * AS + c4 * 4], k + kb + (size_t)row * HD + c4 * 4);
            cpa16(&sV[row * AS + c4 * 4], v + kb + (size_t)row * HD + c4 * 4);
        }
        cp_commit();
    }

    // load + convert Q tile
    {
        size_t qb = (((size_t)b * NH + h) * TT + q0) * HD;
#pragma unroll
        for (int l = 0; l < 8; l++) {
            int idx = tid + l * 256;
            int row = idx >> 4, c4 = idx & 15;
            float4 v4 = *(const float4*)(q + qb + (size_t)row * HD + c4 * 4);
            int base = row * AS + c4 * 4;
            sQ[base + 0] = f2tff(v4.x);
            sQ[base + 1] = f2tff(v4.y);
            sQ[base + 2] = f2tff(v4.z);
            sQ[base + 3] = f2tff(v4.w);
        }
    }
    __syncthreads();

    // per-warp Q fragments (rows wid*16 .. +15); after this sQ region = sP
    const int rw = wid * 16 + g;
    unsigned qa[8][4];
#pragma unroll
    for (int ks = 0; ks < 8; ks++) {
        int kk = ks * 8;
        qa[ks][0] = fu(sQ[rw * AS + kk + t]);
        qa[ks][1] = fu(sQ[(rw + 8) * AS + kk + t]);
        qa[ks][2] = fu(sQ[rw * AS + kk + t + 4]);
        qa[ks][3] = fu(sQ[(rw + 8) * AS + kk + t + 4]);
    }

    float accO[8][4];
#pragma unroll
    for (int j = 0; j < 8; j++)
#pragma unroll
        for (int e = 0; e < 4; e++) accO[j][e] = 0.f;
    float m1 = -1e30f, m2 = -1e30f, l1 = 0.f, l2 = 0.f;

    const int rmin = q0 + wid * 16;
    const int rmax = rmin + 15;
    const int r1 = q0 + rw;
    const int r2 = r1 + 8;

    int stage = 0;
    for (int kt = kt0; kt <= kt1; kt++, stage ^= 1) {
        const int k0 = kt * 64;
        cp_wait0();
        __syncthreads();
        if (kt < kt1) {  // prefetch next tile into other stage
            const int nk0 = (kt + 1) * 64;
            size_t kb = (kvbase + nk0) * HD;
            float* dK = sK + (stage ^ 1) * KVSTG;
            float* dV = sV + (stage ^ 1) * KVSTG;
#pragma unroll
            for (int l = 0; l < 4; l++) {
                int idx = tid + l * 256;
                int row = idx >> 4, c4 = idx & 15;
                cpa16(&dK[row * AS + c4 * 4], k + kb + (size_t)row * HD + c4 * 4);
                cpa16(&dV[row * AS + c4 * 4], v + kb + (size_t)row * HD + c4 * 4);
            }
            cp_commit();
        }
        // in-place RNA convert of the arrived stage
        float* cK = sK + stage * KVSTG;
        float* cV = sV + stage * KVSTG;
#pragma unroll
        for (int l = 0; l < 4; l++) {
            int idx = tid + l * 256;
            int off = (idx >> 4) * AS + (idx & 15) * 4;
            float4 a = *(float4*)&cK[off];
            *(float4*)&cK[off] = make_float4(f2tff(a.x), f2tff(a.y), f2tff(a.z), f2tff(a.w));
            float4 bb4 = *(float4*)&cV[off];
            *(float4*)&cV[off] = make_float4(f2tff(bb4.x), f2tff(bb4.y), f2tff(bb4.z), f2tff(bb4.w));
        }
        __syncthreads();

        // warp-level skip: tile entirely masked for this warp's rows?
        if (k0 > rmax || k0 + 63 < rmin - win) continue;

        // S = Q K^T
        float s[8][4];
#pragma unroll
        for (int j = 0; j < 8; j++)
#pragma unroll
            for (int e = 0; e < 4; e++) s[j][e] = 0.f;
#pragma unroll
        for (int ks = 0; ks < 8; ks++) {
            int kk = ks * 8;
            unsigned bb[8][2];
#pragma unroll
            for (int j = 0; j < 8; j++) {
                int c = j * 8 + g;
                bb[j][0] = fu(cK[c * AS + kk + t]);
                bb[j][1] = fu(cK[c * AS + kk + t + 4]);
            }
#pragma unroll
            for (int j = 0; j < 8; j++)
                mma_tf32(s[j][0], s[j][1], s[j][2], s[j][3],
                         qa[ks][0], qa[ks][1], qa[ks][2], qa[ks][3],
                         bb[j][0], bb[j][1]);
        }

        // mask (scale already folded into q)
        bool full = (k0 + 63 <= rmin) && (rmax - k0 <= win);
        if (!full) {
#pragma unroll
            for (int j = 0; j < 8; j++) {
                int c0 = k0 + j * 8 + 2 * t;
                int d00 = r1 - c0, d01 = d00 - 1;
                int d10 = r2 - c0, d11 = d10 - 1;
                if (!(d00 >= 0 && d00 <= win)) s[j][0] = -1e30f;
                if (!(d01 >= 0 && d01 <= win)) s[j][1] = -1e30f;
                if (!(d10 >= 0 && d10 <= win)) s[j][2] = -1e30f;
                if (!(d11 >= 0 && d11 <= win)) s[j][3] = -1e30f;
            }
        }

        // online softmax
        float mt1 = -1e30f, mt2 = -1e30f;
#pragma unroll
        for (int j = 0; j < 8; j++) {
            mt1 = fmaxf(mt1, fmaxf(s[j][0], s[j][1]));
            mt2 = fmaxf(mt2, fmaxf(s[j][2], s[j][3]));
        }
        mt1 = fmaxf(mt1, __shfl_xor_sync(0xffffffffu, mt1, 1));
        mt1 = fmaxf(mt1, __shfl_xor_sync(0xffffffffu, mt1, 2));
        mt2 = fmaxf(mt2, __shfl_xor_sync(0xffffffffu, mt2, 1));
        mt2 = fmaxf(mt2, __shfl_xor_sync(0xffffffffu, mt2, 2));

        float mn1 = fmaxf(m1, mt1), mn2 = fmaxf(m2, mt2);
        float al1 = __expf(m1 - mn1), al2 = __expf(m2 - mn2);

        float rs1 = 0.f, rs2 = 0.f;
#pragma unroll
        for (int j = 0; j < 8; j++) {
            float p0 = (s[j][0] > -1e29f) ? __expf(s[j][0] - mn1) : 0.f;
            float p1 = (s[j][1] > -1e29f) ? __expf(s[j][1] - mn1) : 0.f;
            float p2 = (s[j][2] > -1e29f) ? __expf(s[j][2] - mn2) : 0.f;
            float p3 = (s[j][3] > -1e29f) ? __expf(s[j][3] - mn2) : 0.f;
            rs1 += p0 + p1; rs2 += p2 + p3;
            int cb = j * 8 + 2 * t;
            *(float2*)&sP[rw * AS + cb]       = make_float2(f2tff(p0), f2tff(p1));
            *(float2*)&sP[(rw + 8) * AS + cb] = make_float2(f2tff(p2), f2tff(p3));
        }
        rs1 += __shfl_xor_sync(0xffffffffu, rs1, 1);
        rs1 += __shfl_xor_sync(0xffffffffu, rs1, 2);
        rs2 += __shfl_xor_sync(0xffffffffu, rs2, 1);
        rs2 += __shfl_xor_sync(0xffffffffu, rs2, 2);

        l1 = l1 * al1 + rs1; m1 = mn1;
        l2 = l2 * al2 + rs2; m2 = mn2;
#pragma unroll
        for (int j = 0; j < 8; j++) {
            accO[j][0] *= al1; accO[j][1] *= al1;
            accO[j][2] *= al2; accO[j][3] *= al2;
        }
        __syncwarp();

        // O += P V
#pragma unroll
        for (int ks = 0; ks < 8; ks++) {
            int kk = ks * 8;
            unsigned pa[4];
            pa[0] = fu(sP[rw * AS + kk + t]);
            pa[1] = fu(sP[(rw + 8) * AS + kk + t]);
            pa[2] = fu(sP[rw * AS + kk + t + 4]);
            pa[3] = fu(sP[(rw + 8) * AS + kk + t + 4]);
            unsigned bb[8][2];
#pragma unroll
            for (int j = 0; j < 8; j++) {
                int d = j * 8 + g;
                bb[j][0] = fu(cV[(kk + t) * AS + d]);
                bb[j][1] = fu(cV[(kk + t + 4) * AS + d]);
            }
#pragma unroll
            for (int j = 0; j < 8; j++)
                mma_tf32(accO[j][0], accO[j][1], accO[j][2], accO[j][3],
                         pa[0], pa[1], pa[2], pa[3], bb[j][0], bb[j][1]);
        }
    }

    // epilogue
    float il1 = 1.0f / l1, il2 = 1.0f / l2;
#pragma unroll
    for (int j = 0; j < 8; j++) {
        int d = h * HD + j * 8 + 2 * t;
        *(float2*)(y + ((size_t)b * TT + r1) * CC + d) =
            make_float2(accO[j][0] * il1, accO[j][1] * il1);
        *(float2*)(y + ((size_t)b * TT + r2) * CC + d) =
            make_float2(accO[j][2] * il2, accO[j][3] * il2);
    }
}

// ---------------- launcher ---------------------------------------------------
extern "C" void kernel_launch(void* const* d_in, const int* in_sizes, int n_in,
                              void* d_out, int out_size) {
    const float* x    = (const float*)d_in[0];
    const float* ve   = (const float*)d_in[1];
    const float* cosp = (const float*)d_in[2];
    const float* sinp = (const float*)d_in[3];
    const float* wq   = (const float*)d_in[4];
    const float* wk   = (const float*)d_in[5];
    const float* wv   = (const float*)d_in[6];
    const float* wo   = (const float*)d_in[7];
    const float* wg   = (const float*)d_in[8];
    const int*   win  = (const int*)d_in[9];
    float* out = (float*)d_out;

    float *qraw, *kraw, *vraw, *qn, *kn, *vn, *att;
    cudaGetSymbolAddress((void**)&qraw, g_qraw);
    cudaGetSymbolAddress((void**)&kraw, g_kraw);
    cudaGetSymbolAddress((void**)&vraw, g_vraw);
    cudaGetSymbolAddress((void**)&qn,   g_qn);
    cudaGetSymbolAddress((void**)&kn,   g_kn);
    cudaGetSymbolAddress((void**)&vn,   g_vn);
    cudaGetSymbolAddress((void**)&att,  g_att);

    // projections
    gemm_tf32<<<dim3(CC / 128, NTOK / 128), 256>>>(x, wq, qraw, CC, CC);
    gemm_kv<<<dim3(4, NTOK / 128), 256>>>(x, wk, wv, kraw, vraw);

    // rotary + rmsnorm + gated ve (+ softmax scale fold)
    postproc<<<NTOK, 256>>>(x, ve, cosp, sinp, wg);

    // attention
    int smem = (QT * AS + 4 * KVSTG) * (int)sizeof(float);  // 110592 B
    cudaFuncSetAttribute(attn_tc, cudaFuncAttributeMaxDynamicSharedMemorySize, smem);
    attn_tc<<<dim3(TT / QT, BB * NH), 256, smem>>>(qn, kn, vn, win, att);

    // output projection
    gemm_tf32<<<dim3(CC / 128, NTOK / 128), 256>>>(att, wo, out, CC, CC);
}

// round 4
// speedup vs baseline: 3.4023x; 1.1081x over previous
#include <cuda_runtime.h>
#include <math.h>

#define BB   4
#define TT   2048
#define CC   1024
#define NH   16
#define NKV  4
#define HD   64
#define NTOK (BB*TT)
#define GATE_CH 12

// ---------------- scratch ----------------------------------------------------
__device__ float g_qraw[NTOK*CC];
__device__ float g_kraw[NTOK*NKV*HD];
__device__ float g_vraw[NTOK*NKV*HD];    // [n][KV*D] raw v projection
__device__ float g_gate[NTOK*NKV];       // sigmoid gate per (token, kv head)
__device__ float g_qn[NTOK*CC];          // [B,H,T,D]  (scale folded in)
__device__ float g_kn[NTOK*NKV*HD];      // [B,KV,T,D]
__device__ float g_vt[NTOK*NKV*HD];      // [B,KV,D,T]  transposed V
__device__ float g_att[NTOK*CC];         // [B,T,H*D]

// ---------------- helpers ----------------------------------------------------
__device__ __forceinline__ unsigned f2tf(float f) {
    unsigned u;
    asm("cvt.rna.tf32.f32 %0, %1;" : "=r"(u) : "f"(f));
    return u;
}
__device__ __forceinline__ float f2tff(float f) { return __uint_as_float(f2tf(f)); }
__device__ __forceinline__ void mma_tf32(float& d0, float& d1, float& d2, float& d3,
                                         unsigned a0, unsigned a1, unsigned a2, unsigned a3,
                                         unsigned b0, unsigned b1) {
    asm volatile(
        "mma.sync.aligned.m16n8k8.row.col.f32.tf32.tf32.f32 "
        "{%0,%1,%2,%3}, {%4,%5,%6,%7}, {%8,%9}, {%0,%1,%2,%3};"
        : "+f"(d0), "+f"(d1), "+f"(d2), "+f"(d3)
        : "r"(a0), "r"(a1), "r"(a2), "r"(a3), "r"(b0), "r"(b1));
}
// one 8x8 b16 ldmatrix tile == one 8x4 tf32 tile, lane l <- (row l>>2, col l&3)
__device__ __forceinline__ void ldsm4(unsigned& r0, unsigned& r1, unsigned& r2, unsigned& r3,
                                      const float* p) {
    unsigned a = (unsigned)__cvta_generic_to_shared(p);
    asm volatile("ldmatrix.sync.aligned.m8n8.x4.shared.b16 {%0,%1,%2,%3}, [%4];"
                 : "=r"(r0), "=r"(r1), "=r"(r2), "=r"(r3) : "r"(a));
}
__device__ __forceinline__ void cpa16(float* s, const float* g) {
    unsigned sa = (unsigned)__cvta_generic_to_shared(s);
    asm volatile("cp.async.cg.shared.global [%0], [%1], 16;" :: "r"(sa), "l"(g));
}
__device__ __forceinline__ void cp_commit() { asm volatile("cp.async.commit_group;"); }
__device__ __forceinline__ void cp_wait0()  { asm volatile("cp.async.wait_group 0;"); }

// ---------------- tf32 NT GEMM body: out[M,N] = A[M,K] * W[N,K]^T ------------
// block 128x128, BK=32, 256 threads = 8 warps (4m x 2n), warp tile 32x64.
#define GS 36
__device__ __forceinline__ void gemm_body(const float* __restrict__ A,
                                          const float* __restrict__ W,
                                          float* __restrict__ out,
                                          int N, int K, int m0, int n0) {
    __shared__ float sA[128 * GS];
    __shared__ float sB[128 * GS];
    const int tid  = threadIdx.x;
    const int lane = tid & 31;
    const int wid  = tid >> 5;
    const int wm = (wid >> 1) * 32, wn = (wid & 1) * 64;
    const int g = lane >> 2, t = lane & 3;
    const int lrow = tid >> 3, lc4 = tid & 7;

    // per-lane ldmatrix base pointers
    const float* pA0 = sA + (wm + (lane & 15)) * GS + (lane >> 4) * 4;
    const float* pB0 = sB + (wn + (lane & 7) + ((lane >> 4) << 3)) * GS + ((lane >> 3) & 1) * 4;

    float acc[2][8][4];
#pragma unroll
    for (int i = 0; i < 2; i++)
#pragma unroll
        for (int j = 0; j < 8; j++)
#pragma unroll
            for (int e = 0; e < 4; e++) acc[i][j][e] = 0.f;

    float4 av[4], bv[4];
#pragma unroll
    for (int l = 0; l < 4; l++) {
        int row = lrow + 32 * l;
        av[l] = *(const float4*)(A + (size_t)(m0 + row) * K + lc4 * 4);
        bv[l] = *(const float4*)(W + (size_t)(n0 + row) * K + lc4 * 4);
    }

    for (int k0 = 0; k0 < K; k0 += 32) {
        __syncthreads();
#pragma unroll
        for (int l = 0; l < 4; l++) {
            int base = (lrow + 32 * l) * GS + lc4 * 4;
            sA[base + 0] = f2tff(av[l].x);
            sA[base + 1] = f2tff(av[l].y);
            sA[base + 2] = f2tff(av[l].z);
            sA[base + 3] = f2tff(av[l].w);
            sB[base + 0] = f2tff(bv[l].x);
            sB[base + 1] = f2tff(bv[l].y);
            sB[base + 2] = f2tff(bv[l].z);
            sB[base + 3] = f2tff(bv[l].w);
        }
        __syncthreads();
        if (k0 + 32 < K) {
#pragma unroll
            for (int l = 0; l < 4; l++) {
                int row = lrow + 32 * l;
                av[l] = *(const float4*)(A + (size_t)(m0 + row) * K + k0 + 32 + lc4 * 4);
                bv[l] = *(const float4*)(W + (size_t)(n0 + row) * K + k0 + 32 + lc4 * 4);
            }
        }
#pragma unroll
        for (int ks = 0; ks < 4; ks++) {
            const int kk = ks * 8;
            unsigned a[2][4];
#pragma unroll
            for (int i = 0; i < 2; i++)
                ldsm4(a[i][0], a[i][1], a[i][2], a[i][3], pA0 + i * 16 * GS + kk);
            unsigned b[8][2];
#pragma unroll
            for (int jp = 0; jp < 4; jp++)
                ldsm4(b[2*jp][0], b[2*jp][1], b[2*jp+1][0], b[2*jp+1][1],
                      pB0 + jp * 16 * GS + kk);
#pragma unroll
            for (int i = 0; i < 2; i++)
#pragma unroll
                for (int j = 0; j < 8; j++)
                    mma_tf32(acc[i][j][0], acc[i][j][1], acc[i][j][2], acc[i][j][3],
                             a[i][0], a[i][1], a[i][2], a[i][3], b[j][0], b[j][1]);
        }
    }
#pragma unroll
    for (int i = 0; i < 2; i++) {
        int r = m0 + wm + i * 16 + g;
#pragma unroll
        for (int j = 0; j < 8; j++) {
            int c = n0 + wn + j * 8 + 2 * t;
            *(float2*)(out + (size_t)r * N + c) = make_float2(acc[i][j][0], acc[i][j][1]);
            *(float2*)(out + (size_t)(r + 8) * N + c) = make_float2(acc[i][j][2], acc[i][j][3]);
        }
    }
}

__global__ __launch_bounds__(256) void gemm_tf32(const float* __restrict__ A,
                                                 const float* __restrict__ W,
                                                 float* __restrict__ out,
                                                 int N, int K) {
    gemm_body(A, W, out, N, K, blockIdx.y * 128, blockIdx.x * 128);
}

__global__ __launch_bounds__(256) void gemm_kv(const float* __restrict__ A,
                                               const float* __restrict__ wk,
                                               const float* __restrict__ wv,
                                               float* __restrict__ kout,
                                               float* __restrict__ vout) {
    const bool isv = blockIdx.x >= 2;
    gemm_body(A, isv ? wv : wk, isv ? vout : kout,
              NKV * HD, CC, blockIdx.y * 128, (blockIdx.x & 1) * 128);
}

// ---------------- rotary + rmsnorm + gate ------------------------------------
__device__ __forceinline__ void rope_norm(const float* __restrict__ in,
                                          float* __restrict__ outp,
                                          int t, int lane, float mult,
                                          const float* __restrict__ cosp,
                                          const float* __restrict__ sinp) {
    float x1 = in[lane];
    float x2 = in[32 + lane];
    float c  = cosp[t * 32 + lane];
    float s  = sinp[t * 32 + lane];
    float o1 =  x1 * c + x2 * s;
    float o2 = -x1 * s + x2 * c;
    float ss = o1 * o1 + o2 * o2;
#pragma unroll
    for (int off = 16; off; off >>= 1) ss += __shfl_xor_sync(0xffffffffu, ss, off);
    float r = rsqrtf(ss * (1.0f / HD) + 1e-6f) * mult;
    outp[lane]      = o1 * r;
    outp[32 + lane] = o2 * r;
}

__global__ __launch_bounds__(256) void postproc(const float* __restrict__ x,
                                                const float* __restrict__ cosp,
                                                const float* __restrict__ sinp,
                                                const float* __restrict__ wgate) {
    const int n = blockIdx.x;
    const int b = n / TT;
    const int t = n % TT;
    const int w    = threadIdx.x >> 5;
    const int lane = threadIdx.x & 31;

#pragma unroll
    for (int h = w; h < NH; h += 8) {
        size_t obase = (((size_t)b * NH + h) * TT + t) * HD;
        rope_norm(g_qraw + (size_t)n * CC + h * HD, g_qn + obase, t, lane,
                  1.15f * 0.125f, cosp, sinp);
    }
    if (w < 4) {
        int h = w;
        size_t obase = (((size_t)b * NKV + h) * TT + t) * HD;
        rope_norm(g_kraw + (size_t)n * NKV * HD + h * HD, g_kn + obase, t, lane,
                  1.15f, cosp, sinp);
    } else {
        int h = w - 4;
        float g = (lane < GATE_CH)
                    ? x[(size_t)n * CC + lane] * wgate[h * GATE_CH + lane] : 0.f;
#pragma unroll
        for (int off = 16; off; off >>= 1) g += __shfl_xor_sync(0xffffffffu, g, off);
        if (lane == 0) g_gate[(size_t)n * NKV + h] = 3.f / (1.f + __expf(-g));
    }
}

// ---------------- V: gate add + transpose to [B,KV,D,T] ----------------------
// grid (TT/32, B*NKV), 256 threads; tile = 32 t x 64 d.
__global__ __launch_bounds__(256) void vtrans(const float* __restrict__ ve) {
    __shared__ float st[32 * 65];
    const int tid = threadIdx.x;
    const int t0  = blockIdx.x * 32;
    const int bkv = blockIdx.y;
    const int b   = bkv >> 2;
    const int kv  = bkv & 3;

#pragma unroll
    for (int l = 0; l < 2; l++) {
        int idx = tid + l * 256;
        int tt = idx >> 4, c4 = idx & 15;
        size_t n = (size_t)b * TT + t0 + tt;
        size_t base = n * (NKV * HD) + kv * HD + c4 * 4;
        float4 vr = *(const float4*)(g_vraw + base);
        float4 vv = *(const float4*)(ve + base);
        float  gg = g_gate[n * NKV + kv];
        st[tt * 65 + c4 * 4 + 0] = vr.x + gg * vv.x;
        st[tt * 65 + c4 * 4 + 1] = vr.y + gg * vv.y;
        st[tt * 65 + c4 * 4 + 2] = vr.z + gg * vv.z;
        st[tt * 65 + c4 * 4 + 3] = vr.w + gg * vv.w;
    }
    __syncthreads();
#pragma unroll
    for (int l = 0; l < 2; l++) {
        int idx = tid + l * 256;
        int d = idx >> 3, tc = idx & 7;
        float4 o = make_float4(st[(tc * 4 + 0) * 65 + d], st[(tc * 4 + 1) * 65 + d],
                               st[(tc * 4 + 2) * 65 + d], st[(tc * 4 + 3) * 65 + d]);
        *(float4*)(g_vt + ((size_t)bkv * HD + d) * TT + t0 + tc * 4) = o;
    }
}

// ---------------- tensor-core sliding-window flash attention -----------------
// grid (T/128, B*H), 256 threads = 8 warps; warp w owns q rows w*16..w*16+15.
#define AS 68
#define QT 128
#define KVSTG (64 * AS)
__global__ __launch_bounds__(256) void attn_tc(const float* __restrict__ q,
                                               const float* __restrict__ k,
                                               const float* __restrict__ v,   // g_vt [B,KV,D,T]
                                               const int* __restrict__ winp,
                                               float* __restrict__ y) {
    extern __shared__ float sm[];
    float* sQ = sm;                    // [r][d] 128x68 (tf32) — dead after frag load
    float* sP = sm;                    // [r][c] 128x68 (tf32) — aliases sQ
    float* sK = sm + QT * AS;          // 2 stages [c][d] 64x68
    float* sV = sK + 2 * KVSTG;        // 2 stages [d][c] 64x68 (transposed V)

    const int tid  = threadIdx.x;
    const int lane = tid & 31;
    const int wid  = tid >> 5;
    const int g = lane >> 2, t = lane & 3;

    const int qt = blockIdx.x;
    const int bh = blockIdx.y;
    const int b  = bh >> 4;
    const int h  = bh & 15;
    const int kvh = h >> 2;
    const int q0  = qt * QT;
    const int win = winp[0];

    int kstart = q0 - win; if (kstart < 0) kstart = 0;
    const int kt0 = kstart >> 6;
    const int kt1 = (q0 + QT - 1) >> 6;

    const size_t kvbase = ((size_t)b * NKV + kvh) * TT;        // k rows base
    const size_t vtbase = ((size_t)b * NKV + kvh) * HD;        // vt rows base

    // ldmatrix per-lane base offsets
    const int ldsmB = ((lane & 7) + ((lane >> 4) << 3)) * AS + ((lane >> 3) & 1) * 4;
    const int ldsmA = (wid * 16 + (lane & 15)) * AS + (lane >> 4) * 4;

    // prologue: first K/V tile
    {
        const int k0 = kt0 * 64;
#pragma unroll
        for (int l = 0; l < 4; l++) {
            int idx = tid + l * 256;
            int row = idx >> 4, c4 = idx & 15;
            cpa16(&sK[row * AS + c4 * 4], k + (kvbase + k0 + row) * HD + c4 * 4);
            cpa16(&sV[row * AS + c4 * 4], v + (vtbase + row) * TT + k0 + c4 * 4);
        }
        cp_commit();
    }

    // load + convert Q tile
    {
        size_t qb = (((size_t)b * NH + h) * TT + q0) * HD;
#pragma unroll
        for (int l = 0; l < 8; l++) {
            int idx = tid + l * 256;
            int row = idx >> 4, c4 = idx & 15;
            float4 v4 = *(const float4*)(q + qb + (size_t)row * HD + c4 * 4);
            int base = row * AS + c4 * 4;
            sQ[base + 0] = f2tff(v4.x);
            sQ[base + 1] = f2tff(v4.y);
            sQ[base + 2] = f2tff(v4.z);
            sQ[base + 3] = f2tff(v4.w);
        }
    }
    __syncthreads();

    unsigned qa[8][4];
#pragma unroll
    for (int ks = 0; ks < 8; ks++)
        ldsm4(qa[ks][0], qa[ks][1], qa[ks][2], qa[ks][3], sQ + ldsmA + ks * 8);

    float accO[8][4];
#pragma unroll
    for (int j = 0; j < 8; j++)
#pragma unroll
        for (int e = 0; e < 4; e++) accO[j][e] = 0.f;
    float m1 = -1e30f, m2 = -1e30f, l1 = 0.f, l2 = 0.f;

    const int rw   = wid * 16 + g;
    const int rmin = q0 + wid * 16;
    const int rmax = rmin + 15;
    const int r1 = q0 + rw;
    const int r2 = r1 + 8;

    int stage = 0;
    for (int kt = kt0; kt <= kt1; kt++, stage ^= 1) {
        const int k0 = kt * 64;
        cp_wait0();
        __syncthreads();
        if (kt < kt1) {
            const int nk0 = (kt + 1) * 64;
            float* dK = sK + (stage ^ 1) * KVSTG;
            float* dV = sV + (stage ^ 1) * KVSTG;
#pragma unroll
            for (int l = 0; l < 4; l++) {
                int idx = tid + l * 256;
                int row = idx >> 4, c4 = idx & 15;
                cpa16(&dK[row * AS + c4 * 4], k + (kvbase + nk0 + row) * HD + c4 * 4);
                cpa16(&dV[row * AS + c4 * 4], v + (vtbase + row) * TT + nk0 + c4 * 4);
            }
            cp_commit();
        }
        float* cK = sK + stage * KVSTG;
        float* cV = sV + stage * KVSTG;
#pragma unroll
        for (int l = 0; l < 4; l++) {
            int idx = tid + l * 256;
            int off = (idx >> 4) * AS + (idx & 15) * 4;
            float4 a = *(float4*)&cK[off];
            *(float4*)&cK[off] = make_float4(f2tff(a.x), f2tff(a.y), f2tff(a.z), f2tff(a.w));
            float4 bb4 = *(float4*)&cV[off];
            *(float4*)&cV[off] = make_float4(f2tff(bb4.x), f2tff(bb4.y), f2tff(bb4.z), f2tff(bb4.w));
        }
        __syncthreads();

        if (k0 > rmax || k0 + 63 < rmin - win) continue;

        // S = Q K^T
        float s[8][4];
#pragma unroll
        for (int j = 0; j < 8; j++)
#pragma unroll
            for (int e = 0; e < 4; e++) s[j][e] = 0.f;
#pragma unroll
        for (int ks = 0; ks < 8; ks++) {
            const int kk = ks * 8;
            unsigned bb[8][2];
#pragma unroll
            for (int jp = 0; jp < 4; jp++)
                ldsm4(bb[2*jp][0], bb[2*jp][1], bb[2*jp+1][0], bb[2*jp+1][1],
                      cK + ldsmB + jp * 16 * AS + kk);
#pragma unroll
            for (int j = 0; j < 8; j++)
                mma_tf32(s[j][0], s[j][1], s[j][2], s[j][3],
                         qa[ks][0], qa[ks][1], qa[ks][2], qa[ks][3],
                         bb[j][0], bb[j][1]);
        }

        // mask
        bool full = (k0 + 63 <= rmin) && (rmax - k0 <= win);
        if (!full) {
#pragma unroll
            for (int j = 0; j < 8; j++) {
                int c0 = k0 + j * 8 + 2 * t;
                int d00 = r1 - c0, d01 = d00 - 1;
                int d10 = r2 - c0, d11 = d10 - 1;
                if (!(d00 >= 0 && d00 <= win)) s[j][0] = -1e30f;
                if (!(d01 >= 0 && d01 <= win)) s[j][1] = -1e30f;
                if (!(d10 >= 0 && d10 <= win)) s[j][2] = -1e30f;
                if (!(d11 >= 0 && d11 <= win)) s[j][3] = -1e30f;
            }
        }

        // online softmax
        float mt1 = -1e30f, mt2 = -1e30f;
#pragma unroll
        for (int j = 0; j < 8; j++) {
            mt1 = fmaxf(mt1, fmaxf(s[j][0], s[j][1]));
            mt2 = fmaxf(mt2, fmaxf(s[j][2], s[j][3]));
        }
        mt1 = fmaxf(mt1, __shfl_xor_sync(0xffffffffu, mt1, 1));
        mt1 = fmaxf(mt1, __shfl_xor_sync(0xffffffffu, mt1, 2));
        mt2 = fmaxf(mt2, __shfl_xor_sync(0xffffffffu, mt2, 1));
        mt2 = fmaxf(mt2, __shfl_xor_sync(0xffffffffu, mt2, 2));

        float mn1 = fmaxf(m1, mt1), mn2 = fmaxf(m2, mt2);
        float al1 = __expf(m1 - mn1), al2 = __expf(m2 - mn2);

        float rs1 = 0.f, rs2 = 0.f;
#pragma unroll
        for (int j = 0; j < 8; j++) {
            float p0 = (s[j][0] > -1e29f) ? __expf(s[j][0] - mn1) : 0.f;
            float p1 = (s[j][1] > -1e29f) ? __expf(s[j][1] - mn1) : 0.f;
            float p2 = (s[j][2] > -1e29f) ? __expf(s[j][2] - mn2) : 0.f;
            float p3 = (s[j][3] > -1e29f) ? __expf(s[j][3] - mn2) : 0.f;
            rs1 += p0 + p1; rs2 += p2 + p3;
            int cb = j * 8 + 2 * t;
            *(float2*)&sP[rw * AS + cb]       = make_float2(f2tff(p0), f2tff(p1));
            *(float2*)&sP[(rw + 8) * AS + cb] = make_float2(f2tff(p2), f2tff(p3));
        }
        rs1 += __shfl_xor_sync(0xffffffffu, rs1, 1);
        rs1 += __shfl_xor_sync(0xffffffffu, rs1, 2);
        rs2 += __shfl_xor_sync(0xffffffffu, rs2, 1);
        rs2 += __shfl_xor_sync(0xffffffffu, rs2, 2);

        l1 = l1 * al1 + rs1; m1 = mn1;
        l2 = l2 * al2 + rs2; m2 = mn2;
#pragma unroll
        for (int j = 0; j < 8; j++) {
            accO[j][0] *= al1; accO[j][1] *= al1;
            accO[j][2] *= al2; accO[j][3] *= al2;
        }
        __syncwarp();

        // O += P V   (V transposed: rows d, cols c)
#pragma unroll
        for (int ks = 0; ks < 8; ks++) {
            const int kk = ks * 8;
            unsigned pa[4];
            ldsm4(pa[0], pa[1], pa[2], pa[3], sP + ldsmA + kk);
            unsigned bb[8][2];
#pragma unroll
            for (int jp = 0; jp < 4; jp++)
                ldsm4(bb[2*jp][0], bb[2*jp][1], bb[2*jp+1][0], bb[2*jp+1][1],
                      cV + ldsmB + jp * 16 * AS + kk);
#pragma unroll
            for (int j = 0; j < 8; j++)
                mma_tf32(accO[j][0], accO[j][1], accO[j][2], accO[j][3],
                         pa[0], pa[1], pa[2], pa[3], bb[j][0], bb[j][1]);
        }
    }

    // epilogue
    float il1 = 1.0f / l1, il2 = 1.0f / l2;
#pragma unroll
    for (int j = 0; j < 8; j++) {
        int d = h * HD + j * 8 + 2 * t;
        *(float2*)(y + ((size_t)b * TT + r1) * CC + d) =
            make_float2(accO[j][0] * il1, accO[j][1] * il1);
        *(float2*)(y + ((size_t)b * TT + r2) * CC + d) =
            make_float2(accO[j][2] * il2, accO[j][3] * il2);
    }
}

// ---------------- launcher ---------------------------------------------------
extern "C" void kernel_launch(void* const* d_in, const int* in_sizes, int n_in,
                              void* d_out, int out_size) {
    const float* x    = (const float*)d_in[0];
    const float* ve   = (const float*)d_in[1];
    const float* cosp = (const float*)d_in[2];
    const float* sinp = (const float*)d_in[3];
    const float* wq   = (const float*)d_in[4];
    const float* wk   = (const float*)d_in[5];
    const float* wv   = (const float*)d_in[6];
    const float* wo   = (const float*)d_in[7];
    const float* wg   = (const float*)d_in[8];
    const int*   win  = (const int*)d_in[9];
    float* out = (float*)d_out;

    float *qraw, *kraw, *vraw, *qn, *kn, *vt, *att;
    cudaGetSymbolAddress((void**)&qraw, g_qraw);
    cudaGetSymbolAddress((void**)&kraw, g_kraw);
    cudaGetSymbolAddress((void**)&vraw, g_vraw);
    cudaGetSymbolAddress((void**)&qn,   g_qn);
    cudaGetSymbolAddress((void**)&kn,   g_kn);
    cudaGetSymbolAddress((void**)&vt,   g_vt);
    cudaGetSymbolAddress((void**)&att,  g_att);

    // projections
    gemm_tf32<<<dim3(CC / 128, NTOK / 128), 256>>>(x, wq, qraw, CC, CC);
    gemm_kv<<<dim3(4, NTOK / 128), 256>>>(x, wk, wv, kraw, vraw);

    // rotary + rmsnorm + gate
    postproc<<<NTOK, 256>>>(x, cosp, sinp, wg);

    // V gate-add + transpose
    vtrans<<<dim3(TT / 32, BB * NKV), 256>>>(ve);

    // attention
    int smem = (QT * AS + 4 * KVSTG) * (int)sizeof(float);  // 104448 B
    cudaFuncSetAttribute(attn_tc, cudaFuncAttributeMaxDynamicSharedMemorySize, smem);
    attn_tc<<<dim3(TT / QT, BB * NH), 256, smem>>>(qn, kn, vt, win, att);

    // output projection
    gemm_tf32<<<dim3(CC / 128, NTOK / 128), 256>>>(att, wo, out, CC, CC);
}

// round 5
// speedup vs baseline: 3.6271x; 1.0661x over previous
#include <cuda_runtime.h>
#include <math.h>

#define BB   4
#define TT   2048
#define CC   1024
#define NH   16
#define NKV  4
#define HD   64
#define NTOK (BB*TT)
#define GATE_CH 12

// ---------------- scratch ----------------------------------------------------
__device__ float g_qraw[NTOK*CC];
__device__ float g_kraw[NTOK*NKV*HD];
__device__ float g_vraw[NTOK*NKV*HD];
__device__ float g_gate[NTOK*NKV];
__device__ float g_qn[NTOK*CC];          // [B,H,T,D] tf32-rounded, scale folded
__device__ float g_kn[NTOK*NKV*HD];      // [B,KV,T,D] tf32-rounded
__device__ float g_vt[NTOK*NKV*HD];      // [B,KV,D,T] tf32-rounded
__device__ float g_att[NTOK*CC];         // [B,T,H*D] tf32-rounded
// pre-rounded GEMM inputs
__device__ float g_xr[NTOK*CC];
__device__ float g_wqr[CC*CC];
__device__ float g_wkr[NKV*HD*CC];
__device__ float g_wvr[NKV*HD*CC];
__device__ float g_wor[CC*CC];

// ---------------- helpers ----------------------------------------------------
__device__ __forceinline__ unsigned f2tf(float f) {
    unsigned u;
    asm("cvt.rna.tf32.f32 %0, %1;" : "=r"(u) : "f"(f));
    return u;
}
__device__ __forceinline__ float f2tff(float f) { return __uint_as_float(f2tf(f)); }
__device__ __forceinline__ void mma_tf32(float& d0, float& d1, float& d2, float& d3,
                                         unsigned a0, unsigned a1, unsigned a2, unsigned a3,
                                         unsigned b0, unsigned b1) {
    asm volatile(
        "mma.sync.aligned.m16n8k8.row.col.f32.tf32.tf32.f32 "
        "{%0,%1,%2,%3}, {%4,%5,%6,%7}, {%8,%9}, {%0,%1,%2,%3};"
        : "+f"(d0), "+f"(d1), "+f"(d2), "+f"(d3)
        : "r"(a0), "r"(a1), "r"(a2), "r"(a3), "r"(b0), "r"(b1));
}
__device__ __forceinline__ void ldsm4(unsigned& r0, unsigned& r1, unsigned& r2, unsigned& r3,
                                      const float* p) {
    unsigned a = (unsigned)__cvta_generic_to_shared(p);
    asm volatile("ldmatrix.sync.aligned.m8n8.x4.shared.b16 {%0,%1,%2,%3}, [%4];"
                 : "=r"(r0), "=r"(r1), "=r"(r2), "=r"(r3) : "r"(a));
}
__device__ __forceinline__ void cpa16(float* s, const float* g) {
    unsigned sa = (unsigned)__cvta_generic_to_shared(s);
    asm volatile("cp.async.cg.shared.global [%0], [%1], 16;" :: "r"(sa), "l"(g));
}
__device__ __forceinline__ void cp_commit() { asm volatile("cp.async.commit_group;"); }
template<int N> __device__ __forceinline__ void cp_wait() {
    asm volatile("cp.async.wait_group %0;" :: "n"(N));
}

// ---------------- elementwise tf32 rounding ----------------------------------
__global__ void cvt_tf32(const float4* __restrict__ s, float4* __restrict__ d, int n4) {
    int i = blockIdx.x * blockDim.x + threadIdx.x;
    int str = gridDim.x * blockDim.x;
    for (; i < n4; i += str) {
        float4 v = s[i];
        d[i] = make_float4(f2tff(v.x), f2tff(v.y), f2tff(v.z), f2tff(v.w));
    }
}

// ---------------- tf32 NT GEMM: out[M,N] = A[M,K] * W[N,K]^T -----------------
// block 128x128, BK=32, 3-stage cp.async pipeline, 256 threads = 8 warps.
// Inputs must be pre-rounded to tf32.
#define GS 36
#define GSTG (128*GS)
__device__ __forceinline__ void gemm_body(const float* __restrict__ A,
                                          const float* __restrict__ W,
                                          float* __restrict__ out,
                                          int N, int K, int m0, int n0) {
    extern __shared__ float gsm[];
    float* smA = gsm;              // 3 stages [row][k] 128x36
    float* smB = gsm + 3 * GSTG;

    const int tid  = threadIdx.x;
    const int lane = tid & 31;
    const int wid  = tid >> 5;
    const int wm = (wid >> 1) * 32, wn = (wid & 1) * 64;
    const int g = lane >> 2, t = lane & 3;
    const int lrow = tid >> 3, lc = tid & 7;

    const int aoff = (wm + (lane & 15)) * GS + (lane >> 4) * 4;
    const int boff = (wn + (lane & 7) + ((lane >> 4) << 3)) * GS + ((lane >> 3) & 1) * 4;

    float acc[2][8][4];
#pragma unroll
    for (int i = 0; i < 2; i++)
#pragma unroll
        for (int j = 0; j < 8; j++)
#pragma unroll
            for (int e = 0; e < 4; e++) acc[i][j][e] = 0.f;

    const int nt = K / 32;

    // preload tiles 0,1
#pragma unroll
    for (int p = 0; p < 2; p++) {
        int k0 = p * 32;
#pragma unroll
        for (int l = 0; l < 4; l++) {
            int idx = tid + l * 256;
            int row = idx >> 3, c = idx & 7;
            cpa16(&smA[p * GSTG + row * GS + c * 4], A + (size_t)(m0 + row) * K + k0 + c * 4);
            cpa16(&smB[p * GSTG + row * GS + c * 4], W + (size_t)(n0 + row) * K + k0 + c * 4);
        }
        cp_commit();
    }
    cp_wait<1>();
    __syncthreads();

    int s = 0;
    for (int i = 0; i < nt; i++) {
        const float* pA = smA + s * GSTG + aoff;
        const float* pB = smB + s * GSTG + boff;
#pragma unroll
        for (int ks = 0; ks < 4; ks++) {
            const int kk = ks * 8;
            unsigned a[2][4];
#pragma unroll
            for (int ii = 0; ii < 2; ii++)
                ldsm4(a[ii][0], a[ii][1], a[ii][2], a[ii][3], pA + ii * 16 * GS + kk);
            unsigned b[8][2];
#pragma unroll
            for (int jp = 0; jp < 4; jp++)
                ldsm4(b[2*jp][0], b[2*jp][1], b[2*jp+1][0], b[2*jp+1][1],
                      pB + jp * 16 * GS + kk);
#pragma unroll
            for (int ii = 0; ii < 2; ii++)
#pragma unroll
                for (int j = 0; j < 8; j++)
                    mma_tf32(acc[ii][j][0], acc[ii][j][1], acc[ii][j][2], acc[ii][j][3],
                             a[ii][0], a[ii][1], a[ii][2], a[ii][3], b[j][0], b[j][1]);
        }
        if (i + 2 < nt) {
            int k0 = (i + 2) * 32;
            int sn = (s + 2) % 3;
#pragma unroll
            for (int l = 0; l < 4; l++) {
                int idx = tid + l * 256;
                int row = idx >> 3, c = idx & 7;
                cpa16(&smA[sn * GSTG + row * GS + c * 4], A + (size_t)(m0 + row) * K + k0 + c * 4);
                cpa16(&smB[sn * GSTG + row * GS + c * 4], W + (size_t)(n0 + row) * K + k0 + c * 4);
            }
            cp_commit();
            cp_wait<1>();
        } else {
            cp_wait<0>();
        }
        __syncthreads();
        s = (s + 1) % 3;
    }
#pragma unroll
    for (int i = 0; i < 2; i++) {
        int r = m0 + wm + i * 16 + g;
#pragma unroll
        for (int j = 0; j < 8; j++) {
            int c = n0 + wn + j * 8 + 2 * t;
            *(float2*)(out + (size_t)r * N + c) = make_float2(acc[i][j][0], acc[i][j][1]);
            *(float2*)(out + (size_t)(r + 8) * N + c) = make_float2(acc[i][j][2], acc[i][j][3]);
        }
    }
}

__global__ __launch_bounds__(256) void gemm_tf32(const float* __restrict__ A,
                                                 const float* __restrict__ W,
                                                 float* __restrict__ out,
                                                 int N, int K) {
    gemm_body(A, W, out, N, K, blockIdx.y * 128, blockIdx.x * 128);
}

__global__ __launch_bounds__(256) void gemm_kv(const float* __restrict__ A,
                                               const float* __restrict__ wk,
                                               const float* __restrict__ wv,
                                               float* __restrict__ kout,
                                               float* __restrict__ vout) {
    const bool isv = blockIdx.x >= 2;
    gemm_body(A, isv ? wv : wk, isv ? vout : kout,
              NKV * HD, CC, blockIdx.y * 128, (blockIdx.x & 1) * 128);
}

// ---------------- rotary + rmsnorm + gate ------------------------------------
__device__ __forceinline__ void rope_norm(const float* __restrict__ in,
                                          float* __restrict__ outp,
                                          int t, int lane, float mult,
                                          const float* __restrict__ cosp,
                                          const float* __restrict__ sinp) {
    float x1 = in[lane];
    float x2 = in[32 + lane];
    float c  = cosp[t * 32 + lane];
    float s  = sinp[t * 32 + lane];
    float o1 =  x1 * c + x2 * s;
    float o2 = -x1 * s + x2 * c;
    float ss = o1 * o1 + o2 * o2;
#pragma unroll
    for (int off = 16; off; off >>= 1) ss += __shfl_xor_sync(0xffffffffu, ss, off);
    float r = rsqrtf(ss * (1.0f / HD) + 1e-6f) * mult;
    outp[lane]      = f2tff(o1 * r);
    outp[32 + lane] = f2tff(o2 * r);
}

__global__ __launch_bounds__(256) void postproc(const float* __restrict__ x,
                                                const float* __restrict__ cosp,
                                                const float* __restrict__ sinp,
                                                const float* __restrict__ wgate) {
    const int n = blockIdx.x;
    const int b = n / TT;
    const int t = n % TT;
    const int w    = threadIdx.x >> 5;
    const int lane = threadIdx.x & 31;

#pragma unroll
    for (int h = w; h < NH; h += 8) {
        size_t obase = (((size_t)b * NH + h) * TT + t) * HD;
        rope_norm(g_qraw + (size_t)n * CC + h * HD, g_qn + obase, t, lane,
                  1.15f * 0.125f, cosp, sinp);
    }
    if (w < 4) {
        int h = w;
        size_t obase = (((size_t)b * NKV + h) * TT + t) * HD;
        rope_norm(g_kraw + (size_t)n * NKV * HD + h * HD, g_kn + obase, t, lane,
                  1.15f, cosp, sinp);
    } else {
        int h = w - 4;
        float g = (lane < GATE_CH)
                    ? x[(size_t)n * CC + lane] * wgate[h * GATE_CH + lane] : 0.f;
#pragma unroll
        for (int off = 16; off; off >>= 1) g += __shfl_xor_sync(0xffffffffu, g, off);
        if (lane == 0) g_gate[(size_t)n * NKV + h] = 3.f / (1.f + __expf(-g));
    }
}

// ---------------- V: gate add + transpose + round ----------------------------
__global__ __launch_bounds__(256) void vtrans(const float* __restrict__ ve) {
    __shared__ float st[32 * 65];
    const int tid = threadIdx.x;
    const int t0  = blockIdx.x * 32;
    const int bkv = blockIdx.y;
    const int b   = bkv >> 2;
    const int kv  = bkv & 3;

#pragma unroll
    for (int l = 0; l < 2; l++) {
        int idx = tid + l * 256;
        int tt = idx >> 4, c4 = idx & 15;
        size_t n = (size_t)b * TT + t0 + tt;
        size_t base = n * (NKV * HD) + kv * HD + c4 * 4;
        float4 vr = *(const float4*)(g_vraw + base);
        float4 vv = *(const float4*)(ve + base);
        float  gg = g_gate[n * NKV + kv];
        st[tt * 65 + c4 * 4 + 0] = f2tff(vr.x + gg * vv.x);
        st[tt * 65 + c4 * 4 + 1] = f2tff(vr.y + gg * vv.y);
        st[tt * 65 + c4 * 4 + 2] = f2tff(vr.z + gg * vv.z);
        st[tt * 65 + c4 * 4 + 3] = f2tff(vr.w + gg * vv.w);
    }
    __syncthreads();
#pragma unroll
    for (int l = 0; l < 2; l++) {
        int idx = tid + l * 256;
        int d = idx >> 3, tc = idx & 7;
        float4 o = make_float4(st[(tc * 4 + 0) * 65 + d], st[(tc * 4 + 1) * 65 + d],
                               st[(tc * 4 + 2) * 65 + d], st[(tc * 4 + 3) * 65 + d]);
        *(float4*)(g_vt + ((size_t)bkv * HD + d) * TT + t0 + tc * 4) = o;
    }
}

// ---------------- tensor-core sliding-window flash attention -----------------
#define AS 68
#define QT 128
#define KVSTG (64 * AS)
__global__ __launch_bounds__(256) void attn_tc(const float* __restrict__ q,
                                               const float* __restrict__ k,
                                               const float* __restrict__ v,   // [B,KV,D,T]
                                               const int* __restrict__ winp,
                                               float* __restrict__ y) {
    extern __shared__ float sm[];
    float* sQ = sm;                    // [r][d] 128x68 — dead after frag load
    float* sP = sm;                    // [r][c] aliases sQ
    float* sK = sm + QT * AS;          // 2 stages [c][d]
    float* sV = sK + 2 * KVSTG;        // 2 stages [d][c]

    const int tid  = threadIdx.x;
    const int lane = tid & 31;
    const int wid  = tid >> 5;
    const int g = lane >> 2, t = lane & 3;

    const int qt = blockIdx.x;
    const int bh = blockIdx.y;
    const int b  = bh >> 4;
    const int h  = bh & 15;
    const int kvh = h >> 2;
    const int q0  = qt * QT;
    const int win = winp[0];

    int kstart = q0 - win; if (kstart < 0) kstart = 0;
    const int kt0 = kstart >> 6;
    const int kt1 = (q0 + QT - 1) >> 6;

    const size_t kvbase = ((size_t)b * NKV + kvh) * TT;
    const size_t vtbase = ((size_t)b * NKV + kvh) * HD;

    const int ldsmB = ((lane & 7) + ((lane >> 4) << 3)) * AS + ((lane >> 3) & 1) * 4;
    const int ldsmA = (wid * 16 + (lane & 15)) * AS + (lane >> 4) * 4;

    // prologue: first K/V tile
    {
        const int k0 = kt0 * 64;
#pragma unroll
        for (int l = 0; l < 4; l++) {
            int idx = tid + l * 256;
            int row = idx >> 4, c4 = idx & 15;
            cpa16(&sK[row * AS + c4 * 4], k + (kvbase + k0 + row) * HD + c4 * 4);
            cpa16(&sV[row * AS + c4 * 4], v + (vtbase + row) * TT + k0 + c4 * 4);
        }
        cp_commit();
    }

    // Q tile (already tf32-rounded in gmem)
    {
        size_t qb = (((size_t)b * NH + h) * TT + q0) * HD;
#pragma unroll
        for (int l = 0; l < 8; l++) {
            int idx = tid + l * 256;
            int row = idx >> 4, c4 = idx & 15;
            *(float4*)&sQ[row * AS + c4 * 4] =
                *(const float4*)(q + qb + (size_t)row * HD + c4 * 4);
        }
    }
    __syncthreads();

    unsigned qa[8][4];
#pragma unroll
    for (int ks = 0; ks < 8; ks++)
        ldsm4(qa[ks][0], qa[ks][1], qa[ks][2], qa[ks][3], sQ + ldsmA + ks * 8);

    float accO[8][4];
#pragma unroll
    for (int j = 0; j < 8; j++)
#pragma unroll
        for (int e = 0; e < 4; e++) accO[j][e] = 0.f;
    float m1 = -1e30f, m2 = -1e30f, l1 = 0.f, l2 = 0.f;

    const int rw   = wid * 16 + g;
    const int rmin = q0 + wid * 16;
    const int rmax = rmin + 15;
    const int r1 = q0 + rw;
    const int r2 = r1 + 8;

    int stage = 0;
    for (int kt = kt0; kt <= kt1; kt++, stage ^= 1) {
        const int k0 = kt * 64;
        cp_wait<0>();
        __syncthreads();
        if (kt < kt1) {
            const int nk0 = (kt + 1) * 64;
            float* dK = sK + (stage ^ 1) * KVSTG;
            float* dV = sV + (stage ^ 1) * KVSTG;
#pragma unroll
            for (int l = 0; l < 4; l++) {
                int idx = tid + l * 256;
                int row = idx >> 4, c4 = idx & 15;
                cpa16(&dK[row * AS + c4 * 4], k + (kvbase + nk0 + row) * HD + c4 * 4);
                cpa16(&dV[row * AS + c4 * 4], v + (vtbase + row) * TT + nk0 + c4 * 4);
            }
            cp_commit();
        }
        if (k0 > rmax || k0 + 63 < rmin - win) continue;

        const float* cK = sK + stage * KVSTG;
        const float* cV = sV + stage * KVSTG;

        // S = Q K^T
        float s[8][4];
#pragma unroll
        for (int j = 0; j < 8; j++)
#pragma unroll
            for (int e = 0; e < 4; e++) s[j][e] = 0.f;
#pragma unroll
        for (int ks = 0; ks < 8; ks++) {
            const int kk = ks * 8;
            unsigned bb[8][2];
#pragma unroll
            for (int jp = 0; jp < 4; jp++)
                ldsm4(bb[2*jp][0], bb[2*jp][1], bb[2*jp+1][0], bb[2*jp+1][1],
                      cK + ldsmB + jp * 16 * AS + kk);
#pragma unroll
            for (int j = 0; j < 8; j++)
                mma_tf32(s[j][0], s[j][1], s[j][2], s[j][3],
                         qa[ks][0], qa[ks][1], qa[ks][2], qa[ks][3],
                         bb[j][0], bb[j][1]);
        }

        bool full = (k0 + 63 <= rmin) && (rmax - k0 <= win);
        if (!full) {
#pragma unroll
            for (int j = 0; j < 8; j++) {
                int c0 = k0 + j * 8 + 2 * t;
                int d00 = r1 - c0, d01 = d00 - 1;
                int d10 = r2 - c0, d11 = d10 - 1;
                if (!(d00 >= 0 && d00 <= win)) s[j][0] = -1e30f;
                if (!(d01 >= 0 && d01 <= win)) s[j][1] = -1e30f;
                if (!(d10 >= 0 && d10 <= win)) s[j][2] = -1e30f;
                if (!(d11 >= 0 && d11 <= win)) s[j][3] = -1e30f;
            }
        }

        float mt1 = -1e30f, mt2 = -1e30f;
#pragma unroll
        for (int j = 0; j < 8; j++) {
            mt1 = fmaxf(mt1, fmaxf(s[j][0], s[j][1]));
            mt2 = fmaxf(mt2, fmaxf(s[j][2], s[j][3]));
        }
        mt1 = fmaxf(mt1, __shfl_xor_sync(0xffffffffu, mt1, 1));
        mt1 = fmaxf(mt1, __shfl_xor_sync(0xffffffffu, mt1, 2));
        mt2 = fmaxf(mt2, __shfl_xor_sync(0xffffffffu, mt2, 1));
        mt2 = fmaxf(mt2, __shfl_xor_sync(0xffffffffu, mt2, 2));

        float mn1 = fmaxf(m1, mt1), mn2 = fmaxf(m2, mt2);
        float al1 = __expf(m1 - mn1), al2 = __expf(m2 - mn2);

        float rs1 = 0.f, rs2 = 0.f;
#pragma unroll
        for (int j = 0; j < 8; j++) {
            float p0 = (s[j][0] > -1e29f) ? __expf(s[j][0] - mn1) : 0.f;
            float p1 = (s[j][1] > -1e29f) ? __expf(s[j][1] - mn1) : 0.f;
            float p2 = (s[j][2] > -1e29f) ? __expf(s[j][2] - mn2) : 0.f;
            float p3 = (s[j][3] > -1e29f) ? __expf(s[j][3] - mn2) : 0.f;
            rs1 += p0 + p1; rs2 += p2 + p3;
            int cb = j * 8 + 2 * t;
            *(float2*)&sP[rw * AS + cb]       = make_float2(f2tff(p0), f2tff(p1));
            *(float2*)&sP[(rw + 8) * AS + cb] = make_float2(f2tff(p2), f2tff(p3));
        }
        rs1 += __shfl_xor_sync(0xffffffffu, rs1, 1);
        rs1 += __shfl_xor_sync(0xffffffffu, rs1, 2);
        rs2 += __shfl_xor_sync(0xffffffffu, rs2, 1);
        rs2 += __shfl_xor_sync(0xffffffffu, rs2, 2);

        l1 = l1 * al1 + rs1; m1 = mn1;
        l2 = l2 * al2 + rs2; m2 = mn2;
#pragma unroll
        for (int j = 0; j < 8; j++) {
            accO[j][0] *= al1; accO[j][1] *= al1;
            accO[j][2] *= al2; accO[j][3] *= al2;
        }
        __syncwarp();

        // O += P V
#pragma unroll
        for (int ks = 0; ks < 8; ks++) {
            const int kk = ks * 8;
            unsigned pa[4];
            ldsm4(pa[0], pa[1], pa[2], pa[3], sP + ldsmA + kk);
            unsigned bb[8][2];
#pragma unroll
            for (int jp = 0; jp < 4; jp++)
                ldsm4(bb[2*jp][0], bb[2*jp][1], bb[2*jp+1][0], bb[2*jp+1][1],
                      cV + ldsmB + jp * 16 * AS + kk);
#pragma unroll
            for (int j = 0; j < 8; j++)
                mma_tf32(accO[j][0], accO[j][1], accO[j][2], accO[j][3],
                         pa[0], pa[1], pa[2], pa[3], bb[j][0], bb[j][1]);
        }
    }

    // epilogue: normalize, round to tf32 (feeds final GEMM), store
    float il1 = 1.0f / l1, il2 = 1.0f / l2;
#pragma unroll
    for (int j = 0; j < 8; j++) {
        int d = h * HD + j * 8 + 2 * t;
        *(float2*)(y + ((size_t)b * TT + r1) * CC + d) =
            make_float2(f2tff(accO[j][0] * il1), f2tff(accO[j][1] * il1));
        *(float2*)(y + ((size_t)b * TT + r2) * CC + d) =
            make_float2(f2tff(accO[j][2] * il2), f2tff(accO[j][3] * il2));
    }
}

// ---------------- launcher ---------------------------------------------------
extern "C" void kernel_launch(void* const* d_in, const int* in_sizes, int n_in,
                              void* d_out, int out_size) {
    const float* x    = (const float*)d_in[0];
    const float* ve   = (const float*)d_in[1];
    const float* cosp = (const float*)d_in[2];
    const float* sinp = (const float*)d_in[3];
    const float* wq   = (const float*)d_in[4];
    const float* wk   = (const float*)d_in[5];
    const float* wv   = (const float*)d_in[6];
    const float* wo   = (const float*)d_in[7];
    const float* wg   = (const float*)d_in[8];
    const int*   win  = (const int*)d_in[9];
    float* out = (float*)d_out;

    float *qraw, *kraw, *vraw, *qn, *kn, *vt, *att;
    float *xr, *wqr, *wkr, *wvr, *wor;
    cudaGetSymbolAddress((void**)&qraw, g_qraw);
    cudaGetSymbolAddress((void**)&kraw, g_kraw);
    cudaGetSymbolAddress((void**)&vraw, g_vraw);
    cudaGetSymbolAddress((void**)&qn,   g_qn);
    cudaGetSymbolAddress((void**)&kn,   g_kn);
    cudaGetSymbolAddress((void**)&vt,   g_vt);
    cudaGetSymbolAddress((void**)&att,  g_att);
    cudaGetSymbolAddress((void**)&xr,   g_xr);
    cudaGetSymbolAddress((void**)&wqr,  g_wqr);
    cudaGetSymbolAddress((void**)&wkr,  g_wkr);
    cudaGetSymbolAddress((void**)&wvr,  g_wvr);
    cudaGetSymbolAddress((void**)&wor,  g_wor);

    // pre-round GEMM inputs to tf32
    cvt_tf32<<<512, 256>>>((const float4*)x,  (float4*)xr,  NTOK * CC / 4);
    cvt_tf32<<<256, 256>>>((const float4*)wq, (float4*)wqr, CC * CC / 4);
    cvt_tf32<<<128, 256>>>((const float4*)wk, (float4*)wkr, NKV * HD * CC / 4);
    cvt_tf32<<<128, 256>>>((const float4*)wv, (float4*)wvr, NKV * HD * CC / 4);
    cvt_tf32<<<256, 256>>>((const float4*)wo, (float4*)wor, CC * CC / 4);

    int gsmem = 6 * GSTG * (int)sizeof(float);  // 110592 B
    cudaFuncSetAttribute(gemm_tf32, cudaFuncAttributeMaxDynamicSharedMemorySize, gsmem);
    cudaFuncSetAttribute(gemm_kv,   cudaFuncAttributeMaxDynamicSharedMemorySize, gsmem);

    // projections
    gemm_tf32<<<dim3(CC / 128, NTOK / 128), 256, gsmem>>>(xr, wqr, qraw, CC, CC);
    gemm_kv<<<dim3(4, NTOK / 128), 256, gsmem>>>(xr, wkr, wvr, kraw, vraw);

    // rotary + rmsnorm + gate
    postproc<<<NTOK, 256>>>(x, cosp, sinp, wg);

    // V gate-add + transpose
    vtrans<<<dim3(TT / 32, BB * NKV), 256>>>(ve);

    // attention
    int smem = (QT * AS + 4 * KVSTG) * (int)sizeof(float);  // 104448 B
    cudaFuncSetAttribute(attn_tc, cudaFuncAttributeMaxDynamicSharedMemorySize, smem);
    attn_tc<<<dim3(TT / QT, BB * NH), 256, smem>>>(qn, kn, vt, win, att);

    // output projection
    gemm_tf32<<<dim3(CC / 128, NTOK / 128), 256, gsmem>>>(att, wor, out, CC, CC);
}